// round 7
// baseline (speedup 1.0000x reference)
#include <cuda_runtime.h>

#define B_    16
#define L_    8192
#define CH_   32
#define NBLK  24
#define TILE  128
#define PSTR  132     // row stride ≡ 4 (mod 32), 16B aligned
#define NTHR  256

typedef unsigned long long u64;

// Scratch (device globals: allocation-free per harness rules)
__device__ float g_hi[B_*L_*CH_];    // init conv output (skip_sum = h_fin - h_init)
__device__ float g_ha[B_*L_*CH_];
__device__ float g_hb[B_*L_*CH_];
__device__ float g_pp[B_*128*8];     // pool partial maxes

// ---- packed f32x2 helpers (FFMA2 is PTX-only; ptxas won't auto-fuse) ------
__device__ __forceinline__ u64 pack2(float a, float b) {
    u64 r; asm("mov.b64 %0, {%1,%2};" : "=l"(r) : "f"(a), "f"(b)); return r;
}
__device__ __forceinline__ void unpack2(u64 v, float& a, float& b) {
    asm("mov.b64 {%0,%1}, %2;" : "=f"(a), "=f"(b) : "l"(v));
}
__device__ __forceinline__ void fma2(u64& d, u64 a, u64 b) {
    asm("fma.rn.f32x2 %0, %1, %2, %0;" : "+l"(d) : "l"(a), "l"(b));
}

struct __align__(16) Smem {
    float4 wq[32][33];     // [c][o] = (wf_tap0, wf_tap1, wg_tap0, wg_tap1)
    float4 w1p[32][9];     // [c][og] = (W1[og][c], W1[og+8][c], W1[og+16][c], W1[og+24][c])
    float  bdf[32], bdg[32], b1s[32];
    float  hTc[32][PSTR];  // [c][pos]
    float  hTp[32][PSTR];  // [c][pos] = h[pos - dil]
    float  gT [32][PSTR];  // gated activations, [c][pos]
};
#define SMEM_BYTES ((int)sizeof(Smem))

// ---------------------------------------------------------------------------
// Initial causal conv (K=2, dil=1): x (B,L) -> h_init (B,L,32)
// ---------------------------------------------------------------------------
__global__ void init_kernel(const float* __restrict__ x,
                            const float* __restrict__ W0,
                            const float* __restrict__ b0) {
    int idx = blockIdx.x * blockDim.x + threadIdx.x;
    if (idx >= B_*L_*CH_) return;
    int c = idx & 31;
    int l = (idx >> 5) & (L_ - 1);
    int b = idx >> 18;
    float xv = x[b*L_ + l];
    float xp = (l > 0) ? x[b*L_ + l - 1] : 0.f;
    g_hi[idx] = fmaf(W0[c*2 + 0], xp, fmaf(W0[c*2 + 1], xv, b0[c]));
}

// ---------------------------------------------------------------------------
// One WaveNet residual block, GEMM-retiled:
//   thread = 4 strided out-channels (og+8*oi) x 4 positions (4*pg..)
//   warp   = 64 outputs (f+g) x 16 positions
// ---------------------------------------------------------------------------
__global__ void __launch_bounds__(NTHR, 2) layer_kernel(
    const float* __restrict__ h_in, float* __restrict__ h_out,
    const float* __restrict__ Wd, const float* __restrict__ bd,
    const float* __restrict__ W1, const float* __restrict__ b1,
    int dil)
{
    extern __shared__ char smem_raw[];
    Smem& S = *reinterpret_cast<Smem*>(smem_raw);

    const int tid = threadIdx.x;
    const int b  = blockIdx.y;
    const int l0 = blockIdx.x * TILE;
    const int base = (b*L_ + l0) * CH_;

    // ---- stage conv weights: Wd is [o][c][2]; pack f+g taps into float4[c][o]
    const float2* Wd2 = (const float2*)Wd;
    #pragma unroll
    for (int i = tid; i < 1024; i += NTHR) {
        int o = i >> 5, c = i & 31;
        float2 vf = Wd2[o*32 + c];          // f-half, coalesced over c
        float2 vg = Wd2[(o+32)*32 + c];     // g-half
        S.wq[c][o] = make_float4(vf.x, vf.y, vg.x, vg.y);
    }
    // ---- stage skip weights, packed for strided-o thread tiles
    {
        int og = tid & 7, c = tid >> 3;     // 256 threads exactly
        S.w1p[c][og] = make_float4(W1[(og     )*32 + c], W1[(og +  8)*32 + c],
                                   W1[(og + 16)*32 + c], W1[(og + 24)*32 + c]);
    }
    if (tid < 32) { S.bdf[tid] = bd[tid]; S.bdg[tid] = bd[32 + tid]; S.b1s[tid] = b1[tid]; }

    // ---- stage h tiles transposed to [c][pos]
    const float* hb = h_in + b*L_*CH_;
    #pragma unroll
    for (int i = tid; i < 1024; i += NTHR) {
        int c = i & 31, lq = (i >> 5) << 2;
        int gi = base + lq*CH_ + c;
        float4 vc;
        vc.x = h_in[gi]; vc.y = h_in[gi+32]; vc.z = h_in[gi+64]; vc.w = h_in[gi+96];
        *(float4*)&S.hTc[c][lq] = vc;
        int lp = l0 + lq - dil;
        float4 vp;
        vp.x = (lp   >= 0) ? hb[(lp  )*CH_ + c] : 0.f;
        vp.y = (lp+1 >= 0) ? hb[(lp+1)*CH_ + c] : 0.f;
        vp.z = (lp+2 >= 0) ? hb[(lp+2)*CH_ + c] : 0.f;
        vp.w = (lp+3 >= 0) ? hb[(lp+3)*CH_ + c] : 0.f;
        *(float4*)&S.hTp[c][lq] = vp;
    }
    __syncthreads();

    const int w   = tid >> 5;
    const int og  = (tid >> 2) & 7;     // lane>>2: output-channel group
    const int pg  = tid & 3;            // lane&3 : position group
    const int pb4 = w*16 + 4*pg;        // this thread's 4 positions

    // ---- dilated conv: accf/accg[oi][pair] over 4 o's x 4 positions
    u64 accf[4][2], accg[4][2];
    #pragma unroll
    for (int oi = 0; oi < 4; oi++) {
        float bf = S.bdf[og + 8*oi], bg = S.bdg[og + 8*oi];
        accf[oi][0] = accf[oi][1] = pack2(bf, bf);
        accg[oi][0] = accg[oi][1] = pack2(bg, bg);
    }
    #pragma unroll 4
    for (int c = 0; c < 32; c++) {
        ulonglong2 hp = *(const ulonglong2*)&S.hTp[c][pb4];
        ulonglong2 hc = *(const ulonglong2*)&S.hTc[c][pb4];
        #pragma unroll
        for (int oi = 0; oi < 4; oi++) {
            float4 wv = S.wq[c][og + 8*oi];
            u64 f0 = pack2(wv.x, wv.x), f1 = pack2(wv.y, wv.y);
            u64 g0 = pack2(wv.z, wv.z), g1 = pack2(wv.w, wv.w);
            fma2(accf[oi][0], f0, hp.x); fma2(accf[oi][0], f1, hc.x);
            fma2(accf[oi][1], f0, hp.y); fma2(accf[oi][1], f1, hc.y);
            fma2(accg[oi][0], g0, hp.x); fma2(accg[oi][0], g1, hc.x);
            fma2(accg[oi][1], g0, hp.y); fma2(accg[oi][1], g1, hc.y);
        }
    }

    // ---- gating: each thread owns matching f,g cells; write gT for skip pass
    #pragma unroll
    for (int oi = 0; oi < 4; oi++) {
        float f0,f1,f2,f3, g0,g1,g2,g3;
        unpack2(accf[oi][0], f0, f1); unpack2(accf[oi][1], f2, f3);
        unpack2(accg[oi][0], g0, g1); unpack2(accg[oi][1], g2, g3);
        float t0 = 1.f - __fdividef(2.f, __expf(2.f*f0) + 1.f);
        float t1 = 1.f - __fdividef(2.f, __expf(2.f*f1) + 1.f);
        float t2 = 1.f - __fdividef(2.f, __expf(2.f*f2) + 1.f);
        float t3 = 1.f - __fdividef(2.f, __expf(2.f*f3) + 1.f);
        float s0 = __fdividef(1.f, 1.f + __expf(-g0));
        float s1 = __fdividef(1.f, 1.f + __expf(-g1));
        float s2 = __fdividef(1.f, 1.f + __expf(-g2));
        float s3 = __fdividef(1.f, 1.f + __expf(-g3));
        *(float4*)&S.gT[og + 8*oi][pb4] = make_float4(t0*s0, t1*s1, t2*s2, t3*s3);
    }
    __syncwarp();   // gT columns [w*16, w*16+16) are entirely warp-local

    // ---- skip = W1 @ gated + b1
    u64 as[4][2];
    #pragma unroll
    for (int oi = 0; oi < 4; oi++) {
        float bs = S.b1s[og + 8*oi];
        as[oi][0] = as[oi][1] = pack2(bs, bs);
    }
    #pragma unroll 4
    for (int c = 0; c < 32; c++) {
        ulonglong2 gg = *(const ulonglong2*)&S.gT[c][pb4];
        float4 wv = S.w1p[c][og];
        u64 w0 = pack2(wv.x, wv.x), w1v = pack2(wv.y, wv.y);
        u64 w2 = pack2(wv.z, wv.z), w3v = pack2(wv.w, wv.w);
        fma2(as[0][0], w0,  gg.x); fma2(as[0][1], w0,  gg.y);
        fma2(as[1][0], w1v, gg.x); fma2(as[1][1], w1v, gg.y);
        fma2(as[2][0], w2,  gg.x); fma2(as[2][1], w2,  gg.y);
        fma2(as[3][0], w3v, gg.x); fma2(as[3][1], w3v, gg.y);
    }

    // ---- residual: h_out = h_in + skip
    #pragma unroll
    for (int oi = 0; oi < 4; oi++) {
        int o = og + 8*oi;
        float4 hv = *(const float4*)&S.hTc[o][pb4];
        float s0,s1,s2,s3;
        unpack2(as[oi][0], s0, s1); unpack2(as[oi][1], s2, s3);
        int gi = base + pb4*CH_ + o;
        h_out[gi]      = hv.x + s0;
        h_out[gi + 32] = hv.y + s1;
        h_out[gi + 64] = hv.z + s2;
        h_out[gi + 96] = hv.w + s3;
    }
}

// ---------------------------------------------------------------------------
// pool: skip_sum = h_fin - h_init; y = relu(Wf@relu(skip)+bf) max-pooled.
// ---------------------------------------------------------------------------
__global__ __launch_bounds__(NTHR) void pool_kernel(
    const float* __restrict__ h_fin, const float* __restrict__ h_init,
    const float* __restrict__ Wf, const float* __restrict__ bf,
    float* __restrict__ pp)
{
    __shared__ float wfT[32][33];
    __shared__ float bfs[32];
    __shared__ float pmax[8][32];
    const int tid = threadIdx.x;
    const int q = blockIdx.x >> 3, s = blockIdx.x & 7;
    const int b = blockIdx.y;

    for (int i = tid; i < 1024; i += NTHR) wfT[i & 31][i >> 5] = Wf[i];
    if (tid < 32) bfs[tid] = bf[tid];
    __syncthreads();

    const int w = tid >> 5, o = tid & 31;
    const int lbase = q * (L_/4) + s * (L_/32);
    float m = 0.f;   // relu folded into max
    for (int p = w; p < L_/32; p += 8) {
        int gi = (b*L_ + lbase + p)*CH_ + o;
        float sv = fmaxf(h_fin[gi] - h_init[gi], 0.f);
        float acc = bfs[o];
        #pragma unroll
        for (int c = 0; c < 32; c++)
            acc = fmaf(wfT[c][o], __shfl_sync(0xffffffffu, sv, c), acc);
        m = fmaxf(m, acc);
    }
    pmax[w][o] = m;
    __syncthreads();
    if (w == 0) {
        float mm = pmax[0][o];
        #pragma unroll
        for (int k = 1; k < 8; k++) mm = fmaxf(mm, pmax[k][o]);
        pp[b*1024 + (o*4 + q)*8 + s] = mm;   // feature index = c*4 + q
    }
}

// ---------------------------------------------------------------------------
// FC head: reduce partials, 128 -> 64 (relu) -> 10
// ---------------------------------------------------------------------------
__global__ void fc_kernel(const float* __restrict__ pp,
                          const float* __restrict__ fW1, const float* __restrict__ fb1,
                          const float* __restrict__ fW2, const float* __restrict__ fb2,
                          float* __restrict__ out)
{
    __shared__ float ps[128], h1[64];
    const int b = blockIdx.x, tid = threadIdx.x;
    #pragma unroll
    for (int f = tid; f < 128; f += 64) {
        const float* p = pp + b*1024 + f*8;
        float m = p[0];
        #pragma unroll
        for (int k = 1; k < 8; k++) m = fmaxf(m, p[k]);
        ps[f] = m;
    }
    __syncthreads();
    float acc = fb1[tid];
    #pragma unroll 8
    for (int k = 0; k < 128; k++) acc = fmaf(fW1[tid*128 + k], ps[k], acc);
    h1[tid] = fmaxf(acc, 0.f);
    __syncthreads();
    if (tid < 10) {
        float a2 = fb2[tid];
        #pragma unroll 8
        for (int k = 0; k < 64; k++) a2 = fmaf(fW2[tid*64 + k], h1[k], a2);
        out[b*10 + tid] = a2;
    }
}

// ---------------------------------------------------------------------------
extern "C" void kernel_launch(void* const* d_in, const int* in_sizes, int n_in,
                              void* d_out, int out_size)
{
    const float* x   = (const float*)d_in[0];
    const float* W0  = (const float*)d_in[1];
    const float* b0  = (const float*)d_in[2];
    const float* Wd  = (const float*)d_in[3];   // (24, 64, 32, 2)
    const float* bd  = (const float*)d_in[4];   // (24, 64)
    const float* W1  = (const float*)d_in[5];   // (24, 32, 32)
    const float* b1  = (const float*)d_in[6];   // (24, 32)
    const float* Wf  = (const float*)d_in[7];
    const float* bf  = (const float*)d_in[8];
    const float* fW1 = (const float*)d_in[9];
    const float* fb1 = (const float*)d_in[10];
    const float* fW2 = (const float*)d_in[11];
    const float* fb2 = (const float*)d_in[12];
    float* out = (float*)d_out;

    static bool attr_done = false;
    if (!attr_done) {
        cudaFuncSetAttribute(layer_kernel,
            cudaFuncAttributeMaxDynamicSharedMemorySize, SMEM_BYTES);
        attr_done = true;
    }

    float *hi, *ha, *hbuf, *pp;
    cudaGetSymbolAddress((void**)&hi,   g_hi);
    cudaGetSymbolAddress((void**)&ha,   g_ha);
    cudaGetSymbolAddress((void**)&hbuf, g_hb);
    cudaGetSymbolAddress((void**)&pp,   g_pp);

    init_kernel<<<(B_*L_*CH_ + 255)/256, 256>>>(x, W0, b0);

    dim3 grid(L_/TILE, B_);
    const float* hin = hi;
    for (int i = 0; i < NBLK; i++) {
        int dil = 1 << (i & 7);
        float* hout = (i & 1) ? hbuf : ha;
        layer_kernel<<<grid, NTHR, SMEM_BYTES>>>(hin, hout,
            Wd + i*64*32*2, bd + i*64, W1 + i*1024, b1 + i*32, dil);
        hin = hout;
    }
    // NBLK=24 even -> final h is in g_hb

    pool_kernel<<<dim3(32, B_), NTHR>>>(hbuf, hi, Wf, bf, pp);
    fc_kernel<<<B_, 64>>>(pp, fW1, fb1, fW2, fb2, out);
}

// round 8
// speedup vs baseline: 1.1087x; 1.1087x over previous
#include <cuda_runtime.h>

#define B_    16
#define L_    8192
#define CH_   32
#define NBLK  24
#define TILE  128
#define PSTR  132     // row stride ≡ 4 (mod 32), 16B aligned
#define NTHR  256

typedef unsigned long long u64;

// Scratch (device globals: allocation-free per harness rules)
__device__ float g_hi[B_*L_*CH_];    // init conv output (skip_sum = h_fin - h_init)
__device__ float g_ha[B_*L_*CH_];
__device__ float g_hb[B_*L_*CH_];
__device__ float g_pp[B_*128*8];     // pool partial maxes

// ---- packed f32x2 helpers (FFMA2 is PTX-only; ptxas won't auto-fuse) ------
__device__ __forceinline__ u64 pack2(float a, float b) {
    u64 r; asm("mov.b64 %0, {%1,%2};" : "=l"(r) : "f"(a), "f"(b)); return r;
}
__device__ __forceinline__ void unpack2(u64 v, float& a, float& b) {
    asm("mov.b64 {%0,%1}, %2;" : "=f"(a), "=f"(b) : "l"(v));
}
__device__ __forceinline__ void fma2(u64& d, u64 a, u64 b) {
    asm("fma.rn.f32x2 %0, %1, %2, %0;" : "+l"(d) : "l"(a), "l"(b));
}

struct __align__(16) Smem {
    float4 wq[32][33];     // [c][o] = (wf_tap0, wf_tap1, wg_tap0, wg_tap1)
    float4 w1p[32][9];     // [c][og] = (W1[og][c], W1[og+8][c], W1[og+16][c], W1[og+24][c])
    float  bdf[32], bdg[32], b1s[32];
    float  hTc[32][PSTR];  // [c][pos]
    float  hTpg[32][PSTR]; // [c][pos]: h[pos-dil] during conv, then REUSED as gated
                           // (safe: each warp touches only its own 16-pos column stripe)
};
#define SMEM_BYTES ((int)sizeof(Smem))

// ---------------------------------------------------------------------------
// Initial causal conv (K=2, dil=1): x (B,L) -> h_init (B,L,32)
// ---------------------------------------------------------------------------
__global__ void init_kernel(const float* __restrict__ x,
                            const float* __restrict__ W0,
                            const float* __restrict__ b0) {
    int idx = blockIdx.x * blockDim.x + threadIdx.x;
    if (idx >= B_*L_*CH_) return;
    int c = idx & 31;
    int l = (idx >> 5) & (L_ - 1);
    int b = idx >> 18;
    float xv = x[b*L_ + l];
    float xp = (l > 0) ? x[b*L_ + l - 1] : 0.f;
    g_hi[idx] = fmaf(W0[c*2 + 0], xp, fmaf(W0[c*2 + 1], xv, b0[c]));
}

// ---------------------------------------------------------------------------
// One WaveNet residual block, GEMM-retiled:
//   thread = 4 strided out-channels (og+8*oi) x 4 positions
//   warp   = 64 outputs (f+g) x 16 positions
// ---------------------------------------------------------------------------
__global__ void __launch_bounds__(NTHR, 3) layer_kernel(
    const float* __restrict__ h_in, float* __restrict__ h_out,
    const float* __restrict__ Wd, const float* __restrict__ bd,
    const float* __restrict__ W1, const float* __restrict__ b1,
    int dil)
{
    extern __shared__ char smem_raw[];
    Smem& S = *reinterpret_cast<Smem*>(smem_raw);

    const int tid = threadIdx.x;
    const int b  = blockIdx.y;
    const int l0 = blockIdx.x * TILE;
    const int base = (b*L_ + l0) * CH_;

    // ---- stage conv weights: Wd is [o][c][2]; pack f+g taps into float4[c][o]
    const float2* Wd2 = (const float2*)Wd;
    #pragma unroll
    for (int i = tid; i < 1024; i += NTHR) {
        int o = i >> 5, c = i & 31;
        float2 vf = Wd2[o*32 + c];          // f-half, coalesced over c
        float2 vg = Wd2[(o+32)*32 + c];     // g-half
        S.wq[c][o] = make_float4(vf.x, vf.y, vg.x, vg.y);
    }
    // ---- stage skip weights, packed for strided-o thread tiles
    {
        int og = tid & 7, c = tid >> 3;     // 256 threads exactly
        S.w1p[c][og] = make_float4(W1[(og     )*32 + c], W1[(og +  8)*32 + c],
                                   W1[(og + 16)*32 + c], W1[(og + 24)*32 + c]);
    }
    if (tid < 32) { S.bdf[tid] = bd[tid]; S.bdg[tid] = bd[32 + tid]; S.b1s[tid] = b1[tid]; }

    // ---- stage h tiles transposed to [c][pos]
    const float* hb = h_in + b*L_*CH_;
    #pragma unroll
    for (int i = tid; i < 1024; i += NTHR) {
        int c = i & 31, lq = (i >> 5) << 2;
        int gi = base + lq*CH_ + c;
        float4 vc;
        vc.x = h_in[gi]; vc.y = h_in[gi+32]; vc.z = h_in[gi+64]; vc.w = h_in[gi+96];
        *(float4*)&S.hTc[c][lq] = vc;
        int lp = l0 + lq - dil;
        float4 vp;
        vp.x = (lp   >= 0) ? hb[(lp  )*CH_ + c] : 0.f;
        vp.y = (lp+1 >= 0) ? hb[(lp+1)*CH_ + c] : 0.f;
        vp.z = (lp+2 >= 0) ? hb[(lp+2)*CH_ + c] : 0.f;
        vp.w = (lp+3 >= 0) ? hb[(lp+3)*CH_ + c] : 0.f;
        *(float4*)&S.hTpg[c][lq] = vp;
    }
    __syncthreads();

    const int w   = tid >> 5;
    const int og  = (tid >> 2) & 7;     // lane>>2: output-channel group
    const int pg  = tid & 3;            // lane&3 : position group
    const int pb4 = w*16 + 4*pg;        // this thread's 4 positions

    // ---- dilated conv: accf/accg[oi][pair] over 4 o's x 4 positions
    u64 accf[4][2], accg[4][2];
    #pragma unroll
    for (int oi = 0; oi < 4; oi++) {
        float bf = S.bdf[og + 8*oi], bg = S.bdg[og + 8*oi];
        accf[oi][0] = accf[oi][1] = pack2(bf, bf);
        accg[oi][0] = accg[oi][1] = pack2(bg, bg);
    }
    #pragma unroll 4
    for (int c = 0; c < 32; c++) {
        ulonglong2 hp = *(const ulonglong2*)&S.hTpg[c][pb4];
        ulonglong2 hc = *(const ulonglong2*)&S.hTc[c][pb4];
        #pragma unroll
        for (int oi = 0; oi < 4; oi++) {
            float4 wv = S.wq[c][og + 8*oi];
            u64 f0 = pack2(wv.x, wv.x), f1 = pack2(wv.y, wv.y);
            u64 g0 = pack2(wv.z, wv.z), g1 = pack2(wv.w, wv.w);
            fma2(accf[oi][0], f0, hp.x); fma2(accf[oi][0], f1, hc.x);
            fma2(accf[oi][1], f0, hp.y); fma2(accf[oi][1], f1, hc.y);
            fma2(accg[oi][0], g0, hp.x); fma2(accg[oi][0], g1, hc.x);
            fma2(accg[oi][1], g0, hp.y); fma2(accg[oi][1], g1, hc.y);
        }
    }

    // ---- gating: tanh(f)*sigmoid(g); write gated into hTpg (hp now dead for
    //      this warp's column stripe -- warp-local reuse, no block sync needed)
    __syncwarp();
    #pragma unroll
    for (int oi = 0; oi < 4; oi++) {
        float f0,f1,f2,f3, g0,g1,g2,g3;
        unpack2(accf[oi][0], f0, f1); unpack2(accf[oi][1], f2, f3);
        unpack2(accg[oi][0], g0, g1); unpack2(accg[oi][1], g2, g3);
        float t0 = 1.f - __fdividef(2.f, __expf(2.f*f0) + 1.f);
        float t1 = 1.f - __fdividef(2.f, __expf(2.f*f1) + 1.f);
        float t2 = 1.f - __fdividef(2.f, __expf(2.f*f2) + 1.f);
        float t3 = 1.f - __fdividef(2.f, __expf(2.f*f3) + 1.f);
        float s0 = __fdividef(1.f, 1.f + __expf(-g0));
        float s1 = __fdividef(1.f, 1.f + __expf(-g1));
        float s2 = __fdividef(1.f, 1.f + __expf(-g2));
        float s3 = __fdividef(1.f, 1.f + __expf(-g3));
        *(float4*)&S.hTpg[og + 8*oi][pb4] = make_float4(t0*s0, t1*s1, t2*s2, t3*s3);
    }
    __syncwarp();   // gated columns [w*16, w*16+16) are entirely warp-local

    // ---- skip = W1 @ gated + b1
    u64 as[4][2];
    #pragma unroll
    for (int oi = 0; oi < 4; oi++) {
        float bs = S.b1s[og + 8*oi];
        as[oi][0] = as[oi][1] = pack2(bs, bs);
    }
    #pragma unroll 4
    for (int c = 0; c < 32; c++) {
        ulonglong2 gg = *(const ulonglong2*)&S.hTpg[c][pb4];
        float4 wv = S.w1p[c][og];
        u64 w0 = pack2(wv.x, wv.x), w1v = pack2(wv.y, wv.y);
        u64 w2 = pack2(wv.z, wv.z), w3v = pack2(wv.w, wv.w);
        fma2(as[0][0], w0,  gg.x); fma2(as[0][1], w0,  gg.y);
        fma2(as[1][0], w1v, gg.x); fma2(as[1][1], w1v, gg.y);
        fma2(as[2][0], w2,  gg.x); fma2(as[2][1], w2,  gg.y);
        fma2(as[3][0], w3v, gg.x); fma2(as[3][1], w3v, gg.y);
    }

    // ---- residual: h_out = h_in + skip
    #pragma unroll
    for (int oi = 0; oi < 4; oi++) {
        int o = og + 8*oi;
        float4 hv = *(const float4*)&S.hTc[o][pb4];
        float s0,s1,s2,s3;
        unpack2(as[oi][0], s0, s1); unpack2(as[oi][1], s2, s3);
        int gi = base + pb4*CH_ + o;
        h_out[gi]      = hv.x + s0;
        h_out[gi + 32] = hv.y + s1;
        h_out[gi + 64] = hv.z + s2;
        h_out[gi + 96] = hv.w + s3;
    }
}

// ---------------------------------------------------------------------------
// pool: skip_sum = h_fin - h_init; y = relu(Wf@relu(skip)+bf) max-pooled.
// ---------------------------------------------------------------------------
__global__ __launch_bounds__(NTHR) void pool_kernel(
    const float* __restrict__ h_fin, const float* __restrict__ h_init,
    const float* __restrict__ Wf, const float* __restrict__ bf,
    float* __restrict__ pp)
{
    __shared__ float wfT[32][33];
    __shared__ float bfs[32];
    __shared__ float pmax[8][32];
    const int tid = threadIdx.x;
    const int q = blockIdx.x >> 3, s = blockIdx.x & 7;
    const int b = blockIdx.y;

    for (int i = tid; i < 1024; i += NTHR) wfT[i & 31][i >> 5] = Wf[i];
    if (tid < 32) bfs[tid] = bf[tid];
    __syncthreads();

    const int w = tid >> 5, o = tid & 31;
    const int lbase = q * (L_/4) + s * (L_/32);
    float m = 0.f;   // relu folded into max
    for (int p = w; p < L_/32; p += 8) {
        int gi = (b*L_ + lbase + p)*CH_ + o;
        float sv = fmaxf(h_fin[gi] - h_init[gi], 0.f);
        float acc = bfs[o];
        #pragma unroll
        for (int c = 0; c < 32; c++)
            acc = fmaf(wfT[c][o], __shfl_sync(0xffffffffu, sv, c), acc);
        m = fmaxf(m, acc);
    }
    pmax[w][o] = m;
    __syncthreads();
    if (w == 0) {
        float mm = pmax[0][o];
        #pragma unroll
        for (int k = 1; k < 8; k++) mm = fmaxf(mm, pmax[k][o]);
        pp[b*1024 + (o*4 + q)*8 + s] = mm;   // feature index = c*4 + q
    }
}

// ---------------------------------------------------------------------------
// FC head: reduce partials, 128 -> 64 (relu) -> 10
// ---------------------------------------------------------------------------
__global__ void fc_kernel(const float* __restrict__ pp,
                          const float* __restrict__ fW1, const float* __restrict__ fb1,
                          const float* __restrict__ fW2, const float* __restrict__ fb2,
                          float* __restrict__ out)
{
    __shared__ float ps[128], h1[64];
    const int b = blockIdx.x, tid = threadIdx.x;
    #pragma unroll
    for (int f = tid; f < 128; f += 64) {
        const float* p = pp + b*1024 + f*8;
        float m = p[0];
        #pragma unroll
        for (int k = 1; k < 8; k++) m = fmaxf(m, p[k]);
        ps[f] = m;
    }
    __syncthreads();
    float acc = fb1[tid];
    #pragma unroll 8
    for (int k = 0; k < 128; k++) acc = fmaf(fW1[tid*128 + k], ps[k], acc);
    h1[tid] = fmaxf(acc, 0.f);
    __syncthreads();
    if (tid < 10) {
        float a2 = fb2[tid];
        #pragma unroll 8
        for (int k = 0; k < 64; k++) a2 = fmaf(fW2[tid*64 + k], h1[k], a2);
        out[b*10 + tid] = a2;
    }
}

// ---------------------------------------------------------------------------
extern "C" void kernel_launch(void* const* d_in, const int* in_sizes, int n_in,
                              void* d_out, int out_size)
{
    const float* x   = (const float*)d_in[0];
    const float* W0  = (const float*)d_in[1];
    const float* b0  = (const float*)d_in[2];
    const float* Wd  = (const float*)d_in[3];   // (24, 64, 32, 2)
    const float* bd  = (const float*)d_in[4];   // (24, 64)
    const float* W1  = (const float*)d_in[5];   // (24, 32, 32)
    const float* b1  = (const float*)d_in[6];   // (24, 32)
    const float* Wf  = (const float*)d_in[7];
    const float* bf  = (const float*)d_in[8];
    const float* fW1 = (const float*)d_in[9];
    const float* fb1 = (const float*)d_in[10];
    const float* fW2 = (const float*)d_in[11];
    const float* fb2 = (const float*)d_in[12];
    float* out = (float*)d_out;

    static bool attr_done = false;
    if (!attr_done) {
        cudaFuncSetAttribute(layer_kernel,
            cudaFuncAttributeMaxDynamicSharedMemorySize, SMEM_BYTES);
        attr_done = true;
    }

    float *hi, *ha, *hbuf, *pp;
    cudaGetSymbolAddress((void**)&hi,   g_hi);
    cudaGetSymbolAddress((void**)&ha,   g_ha);
    cudaGetSymbolAddress((void**)&hbuf, g_hb);
    cudaGetSymbolAddress((void**)&pp,   g_pp);

    init_kernel<<<(B_*L_*CH_ + 255)/256, 256>>>(x, W0, b0);

    dim3 grid(L_/TILE, B_);
    const float* hin = hi;
    for (int i = 0; i < NBLK; i++) {
        int dil = 1 << (i & 7);
        float* hout = (i & 1) ? hbuf : ha;
        layer_kernel<<<grid, NTHR, SMEM_BYTES>>>(hin, hout,
            Wd + i*64*32*2, bd + i*64, W1 + i*1024, b1 + i*32, dil);
        hin = hout;
    }
    // NBLK=24 even -> final h is in g_hb

    pool_kernel<<<dim3(32, B_), NTHR>>>(hbuf, hi, Wf, bf, pp);
    fc_kernel<<<B_, 64>>>(pp, fW1, fb1, fW2, fb2, out);
}

// round 9
// speedup vs baseline: 1.1338x; 1.0226x over previous
#include <cuda_runtime.h>

#define B_    16
#define L_    8192
#define CH_   32
#define NBLK  24
#define TILE  128
#define PSTR  132     // row stride ≡ 4 (mod 32), 16B aligned
#define NTHR  256

typedef unsigned long long u64;

// Scratch (device globals: allocation-free per harness rules)
__device__ float g_hi[B_*L_*CH_];    // init conv output (skip_sum = h_fin - h_init)
__device__ float g_ha[B_*L_*CH_];
__device__ float g_hb[B_*L_*CH_];
__device__ float g_pp[B_*128*8];     // pool partial maxes

// ---- packed f32x2 helpers (FFMA2 is PTX-only; ptxas won't auto-fuse) ------
__device__ __forceinline__ u64 pack2(float a, float b) {
    u64 r; asm("mov.b64 %0, {%1,%2};" : "=l"(r) : "f"(a), "f"(b)); return r;
}
__device__ __forceinline__ void unpack2(u64 v, float& a, float& b) {
    asm("mov.b64 {%0,%1}, %2;" : "=f"(a), "=f"(b) : "l"(v));
}
__device__ __forceinline__ void fma2(u64& d, u64 a, u64 b) {
    asm("fma.rn.f32x2 %0, %1, %2, %0;" : "+l"(d) : "l"(a), "l"(b));
}

// Channel-pair packed weights: FFMA2 weight operands come straight from LDS.
struct __align__(16) Smem {
    // wq[c][j]: j<16 -> f-pair j = channels (2j,2j+1); j>=16 -> g-pair (j-16).
    // float4 = (tap0[lo], tap0[hi], tap1[lo], tap1[hi]); as ulonglong2:
    // .x = tap0 packed pair, .y = tap1 packed pair.
    float4 wq[32][33];
    // w1q[c][og] = (W1[2og][c], W1[2og+1][c], W1[2og+16][c], W1[2og+17][c])
    float4 w1q[32][8];
    float  bdf[32], bdg[32], b1s[32];
    float  hTc[32][PSTR];   // [c][pos]
    float  hTpg[32][PSTR];  // h[pos-dil] during conv, then reused for gated
};
#define SMEM_BYTES ((int)sizeof(Smem))

// ---------------------------------------------------------------------------
// Initial causal conv (K=2, dil=1): x (B,L) -> h_init (B,L,32)
// ---------------------------------------------------------------------------
__global__ void init_kernel(const float* __restrict__ x,
                            const float* __restrict__ W0,
                            const float* __restrict__ b0) {
    int idx = blockIdx.x * blockDim.x + threadIdx.x;
    if (idx >= B_*L_*CH_) return;
    int c = idx & 31;
    int l = (idx >> 5) & (L_ - 1);
    int b = idx >> 18;
    float xv = x[b*L_ + l];
    float xp = (l > 0) ? x[b*L_ + l - 1] : 0.f;
    g_hi[idx] = fmaf(W0[c*2 + 0], xp, fmaf(W0[c*2 + 1], xv, b0[c]));
}

// ---------------------------------------------------------------------------
// One WaveNet residual block. Thread tile: channel-pairs {2og,2og+1} and
// {2og+16,2og+17} (f and g) x 4 positions. FFMA2 packed over channel pairs.
// ---------------------------------------------------------------------------
__global__ void __launch_bounds__(NTHR, 4) layer_kernel(
    const float* __restrict__ h_in, float* __restrict__ h_out,
    const float* __restrict__ Wd, const float* __restrict__ bd,
    const float* __restrict__ W1, const float* __restrict__ b1,
    int dil)
{
    extern __shared__ char smem_raw[];
    Smem& S = *reinterpret_cast<Smem*>(smem_raw);

    const int tid = threadIdx.x;
    const int b  = blockIdx.y;
    const int l0 = blockIdx.x * TILE;
    const int base = (b*L_ + l0) * CH_;

    // ---- stage conv weights as channel-pair float4s
    const float2* Wd2 = (const float2*)Wd;    // Wd[o][c][2] -> float2 taps
    #pragma unroll
    for (int i = tid; i < 1024; i += NTHR) {
        int j = i >> 5, c = i & 31;
        int o0 = 2*(j & 15) + ((j >= 16) ? 32 : 0);
        float2 wa = Wd2[o0*32 + c];
        float2 wb = Wd2[(o0+1)*32 + c];
        S.wq[c][j] = make_float4(wa.x, wb.x, wa.y, wb.y);
    }
    {   // skip weights, channel-pair packed (256 threads exactly)
        int og = tid & 7, c = tid >> 3;
        S.w1q[c][og] = make_float4(W1[(2*og   )*32 + c], W1[(2*og+ 1)*32 + c],
                                   W1[(2*og+16)*32 + c], W1[(2*og+17)*32 + c]);
    }
    if (tid < 32) { S.bdf[tid] = bd[tid]; S.bdg[tid] = bd[32 + tid]; S.b1s[tid] = b1[tid]; }

    // ---- stage h tiles transposed to [c][pos]
    const float* hb = h_in + b*L_*CH_;
    #pragma unroll
    for (int i = tid; i < 1024; i += NTHR) {
        int c = i & 31, lq = (i >> 5) << 2;
        int gi = base + lq*CH_ + c;
        float4 vc;
        vc.x = h_in[gi]; vc.y = h_in[gi+32]; vc.z = h_in[gi+64]; vc.w = h_in[gi+96];
        *(float4*)&S.hTc[c][lq] = vc;
        int lp = l0 + lq - dil;
        float4 vp;
        vp.x = (lp   >= 0) ? hb[(lp  )*CH_ + c] : 0.f;
        vp.y = (lp+1 >= 0) ? hb[(lp+1)*CH_ + c] : 0.f;
        vp.z = (lp+2 >= 0) ? hb[(lp+2)*CH_ + c] : 0.f;
        vp.w = (lp+3 >= 0) ? hb[(lp+3)*CH_ + c] : 0.f;
        *(float4*)&S.hTpg[c][lq] = vp;
    }
    __syncthreads();

    const int w   = tid >> 5;
    const int og  = (tid >> 2) & 7;     // channel-pair group
    const int pg  = tid & 3;            // position group
    const int pb4 = w*16 + 4*pg;        // this thread's 4 positions

    // ---- dilated conv: acc = packed channel-pair, per position
    u64 accfA[4], accfB[4], accgA[4], accgB[4];
    {
        u64 bfA = *(const u64*)&S.bdf[2*og], bfB = *(const u64*)&S.bdf[2*og+16];
        u64 bgA = *(const u64*)&S.bdg[2*og], bgB = *(const u64*)&S.bdg[2*og+16];
        #pragma unroll
        for (int k = 0; k < 4; k++) {
            accfA[k] = bfA; accfB[k] = bfB; accgA[k] = bgA; accgB[k] = bgB;
        }
    }
    #pragma unroll 4
    for (int c = 0; c < 32; c++) {
        float4 hp4 = *(const float4*)&S.hTpg[c][pb4];
        float4 hc4 = *(const float4*)&S.hTc[c][pb4];
        u64 dp[4], dc[4];
        dp[0] = pack2(hp4.x, hp4.x); dp[1] = pack2(hp4.y, hp4.y);
        dp[2] = pack2(hp4.z, hp4.z); dp[3] = pack2(hp4.w, hp4.w);
        dc[0] = pack2(hc4.x, hc4.x); dc[1] = pack2(hc4.y, hc4.y);
        dc[2] = pack2(hc4.z, hc4.z); dc[3] = pack2(hc4.w, hc4.w);
        ulonglong2 wfA = *(const ulonglong2*)&S.wq[c][og];
        #pragma unroll
        for (int k = 0; k < 4; k++) { fma2(accfA[k], wfA.x, dp[k]); fma2(accfA[k], wfA.y, dc[k]); }
        ulonglong2 wfB = *(const ulonglong2*)&S.wq[c][og + 8];
        #pragma unroll
        for (int k = 0; k < 4; k++) { fma2(accfB[k], wfB.x, dp[k]); fma2(accfB[k], wfB.y, dc[k]); }
        ulonglong2 wgA = *(const ulonglong2*)&S.wq[c][16 + og];
        #pragma unroll
        for (int k = 0; k < 4; k++) { fma2(accgA[k], wgA.x, dp[k]); fma2(accgA[k], wgA.y, dc[k]); }
        ulonglong2 wgB = *(const ulonglong2*)&S.wq[c][24 + og];
        #pragma unroll
        for (int k = 0; k < 4; k++) { fma2(accgB[k], wgB.x, dp[k]); fma2(accgB[k], wgB.y, dc[k]); }
    }

    // ---- gating: tanh(f)*sigmoid(g); write gated rows into hTpg (reuse).
    // All conv reads of this warp's column stripe complete before writes.
    __syncwarp();
    {
        float rA0[4], rA1[4], rB0[4], rB1[4];
        #pragma unroll
        for (int k = 0; k < 4; k++) {
            float fa0, fa1, ga0, ga1, fb0, fb1, gb0, gb1;
            unpack2(accfA[k], fa0, fa1); unpack2(accgA[k], ga0, ga1);
            unpack2(accfB[k], fb0, fb1); unpack2(accgB[k], gb0, gb1);
            float tA0 = 1.f - __fdividef(2.f, __expf(2.f*fa0) + 1.f);
            float tA1 = 1.f - __fdividef(2.f, __expf(2.f*fa1) + 1.f);
            float tB0 = 1.f - __fdividef(2.f, __expf(2.f*fb0) + 1.f);
            float tB1 = 1.f - __fdividef(2.f, __expf(2.f*fb1) + 1.f);
            float sA0 = __fdividef(1.f, 1.f + __expf(-ga0));
            float sA1 = __fdividef(1.f, 1.f + __expf(-ga1));
            float sB0 = __fdividef(1.f, 1.f + __expf(-gb0));
            float sB1 = __fdividef(1.f, 1.f + __expf(-gb1));
            rA0[k] = tA0*sA0; rA1[k] = tA1*sA1; rB0[k] = tB0*sB0; rB1[k] = tB1*sB1;
        }
        *(float4*)&S.hTpg[2*og   ][pb4] = make_float4(rA0[0], rA0[1], rA0[2], rA0[3]);
        *(float4*)&S.hTpg[2*og+ 1][pb4] = make_float4(rA1[0], rA1[1], rA1[2], rA1[3]);
        *(float4*)&S.hTpg[2*og+16][pb4] = make_float4(rB0[0], rB0[1], rB0[2], rB0[3]);
        *(float4*)&S.hTpg[2*og+17][pb4] = make_float4(rB1[0], rB1[1], rB1[2], rB1[3]);
    }
    __syncwarp();   // gated columns [w*16, w*16+16) are entirely warp-local

    // ---- skip = W1 @ gated + b1 (channel-pair packed; weights direct from LDS)
    u64 accsA[4], accsB[4];
    {
        u64 bsA = *(const u64*)&S.b1s[2*og], bsB = *(const u64*)&S.b1s[2*og+16];
        #pragma unroll
        for (int k = 0; k < 4; k++) { accsA[k] = bsA; accsB[k] = bsB; }
    }
    #pragma unroll 4
    for (int c = 0; c < 32; c++) {
        float4 gg = *(const float4*)&S.hTpg[c][pb4];
        u64 d0 = pack2(gg.x, gg.x), d1 = pack2(gg.y, gg.y);
        u64 d2 = pack2(gg.z, gg.z), d3 = pack2(gg.w, gg.w);
        ulonglong2 wp = *(const ulonglong2*)&S.w1q[c][og];
        fma2(accsA[0], wp.x, d0); fma2(accsB[0], wp.y, d0);
        fma2(accsA[1], wp.x, d1); fma2(accsB[1], wp.y, d1);
        fma2(accsA[2], wp.x, d2); fma2(accsB[2], wp.y, d2);
        fma2(accsA[3], wp.x, d3); fma2(accsB[3], wp.y, d3);
    }

    // ---- residual: h_out = h_in + skip; adjacent channel pairs -> STG.64
    {
        float4 h0 = *(const float4*)&S.hTc[2*og   ][pb4];
        float4 h1 = *(const float4*)&S.hTc[2*og+ 1][pb4];
        float4 h2 = *(const float4*)&S.hTc[2*og+16][pb4];
        float4 h3 = *(const float4*)&S.hTc[2*og+17][pb4];
        float h0a[4] = {h0.x,h0.y,h0.z,h0.w}, h1a[4] = {h1.x,h1.y,h1.z,h1.w};
        float h2a[4] = {h2.x,h2.y,h2.z,h2.w}, h3a[4] = {h3.x,h3.y,h3.z,h3.w};
        #pragma unroll
        for (int k = 0; k < 4; k++) {
            float sa0, sa1, sb0, sb1;
            unpack2(accsA[k], sa0, sa1);
            unpack2(accsB[k], sb0, sb1);
            int gi = base + (pb4 + k)*CH_;
            *(float2*)&h_out[gi + 2*og]      = make_float2(h0a[k] + sa0, h1a[k] + sa1);
            *(float2*)&h_out[gi + 2*og + 16] = make_float2(h2a[k] + sb0, h3a[k] + sb1);
        }
    }
}

// ---------------------------------------------------------------------------
// pool: skip_sum = h_fin - h_init; y = relu(Wf@relu(skip)+bf) max-pooled.
// ---------------------------------------------------------------------------
__global__ __launch_bounds__(NTHR) void pool_kernel(
    const float* __restrict__ h_fin, const float* __restrict__ h_init,
    const float* __restrict__ Wf, const float* __restrict__ bf,
    float* __restrict__ pp)
{
    __shared__ float wfT[32][33];
    __shared__ float bfs[32];
    __shared__ float pmax[8][32];
    const int tid = threadIdx.x;
    const int q = blockIdx.x >> 3, s = blockIdx.x & 7;
    const int b = blockIdx.y;

    for (int i = tid; i < 1024; i += NTHR) wfT[i & 31][i >> 5] = Wf[i];
    if (tid < 32) bfs[tid] = bf[tid];
    __syncthreads();

    const int w = tid >> 5, o = tid & 31;
    const int lbase = q * (L_/4) + s * (L_/32);
    float m = 0.f;   // relu folded into max
    for (int p = w; p < L_/32; p += 8) {
        int gi = (b*L_ + lbase + p)*CH_ + o;
        float sv = fmaxf(h_fin[gi] - h_init[gi], 0.f);
        float acc = bfs[o];
        #pragma unroll
        for (int c = 0; c < 32; c++)
            acc = fmaf(wfT[c][o], __shfl_sync(0xffffffffu, sv, c), acc);
        m = fmaxf(m, acc);
    }
    pmax[w][o] = m;
    __syncthreads();
    if (w == 0) {
        float mm = pmax[0][o];
        #pragma unroll
        for (int k = 1; k < 8; k++) mm = fmaxf(mm, pmax[k][o]);
        pp[b*1024 + (o*4 + q)*8 + s] = mm;   // feature index = c*4 + q
    }
}

// ---------------------------------------------------------------------------
// FC head: reduce partials, 128 -> 64 (relu) -> 10
// ---------------------------------------------------------------------------
__global__ void fc_kernel(const float* __restrict__ pp,
                          const float* __restrict__ fW1, const float* __restrict__ fb1,
                          const float* __restrict__ fW2, const float* __restrict__ fb2,
                          float* __restrict__ out)
{
    __shared__ float ps[128], h1[64];
    const int b = blockIdx.x, tid = threadIdx.x;
    #pragma unroll
    for (int f = tid; f < 128; f += 64) {
        const float* p = pp + b*1024 + f*8;
        float m = p[0];
        #pragma unroll
        for (int k = 1; k < 8; k++) m = fmaxf(m, p[k]);
        ps[f] = m;
    }
    __syncthreads();
    float acc = fb1[tid];
    #pragma unroll 8
    for (int k = 0; k < 128; k++) acc = fmaf(fW1[tid*128 + k], ps[k], acc);
    h1[tid] = fmaxf(acc, 0.f);
    __syncthreads();
    if (tid < 10) {
        float a2 = fb2[tid];
        #pragma unroll 8
        for (int k = 0; k < 64; k++) a2 = fmaf(fW2[tid*64 + k], h1[k], a2);
        out[b*10 + tid] = a2;
    }
}

// ---------------------------------------------------------------------------
extern "C" void kernel_launch(void* const* d_in, const int* in_sizes, int n_in,
                              void* d_out, int out_size)
{
    const float* x   = (const float*)d_in[0];
    const float* W0  = (const float*)d_in[1];
    const float* b0  = (const float*)d_in[2];
    const float* Wd  = (const float*)d_in[3];   // (24, 64, 32, 2)
    const float* bd  = (const float*)d_in[4];   // (24, 64)
    const float* W1  = (const float*)d_in[5];   // (24, 32, 32)
    const float* b1  = (const float*)d_in[6];   // (24, 32)
    const float* Wf  = (const float*)d_in[7];
    const float* bf  = (const float*)d_in[8];
    const float* fW1 = (const float*)d_in[9];
    const float* fb1 = (const float*)d_in[10];
    const float* fW2 = (const float*)d_in[11];
    const float* fb2 = (const float*)d_in[12];
    float* out = (float*)d_out;

    static bool attr_done = false;
    if (!attr_done) {
        cudaFuncSetAttribute(layer_kernel,
            cudaFuncAttributeMaxDynamicSharedMemorySize, SMEM_BYTES);
        attr_done = true;
    }

    float *hi, *ha, *hbuf, *pp;
    cudaGetSymbolAddress((void**)&hi,   g_hi);
    cudaGetSymbolAddress((void**)&ha,   g_ha);
    cudaGetSymbolAddress((void**)&hbuf, g_hb);
    cudaGetSymbolAddress((void**)&pp,   g_pp);

    init_kernel<<<(B_*L_*CH_ + 255)/256, 256>>>(x, W0, b0);

    dim3 grid(L_/TILE, B_);
    const float* hin = hi;
    for (int i = 0; i < NBLK; i++) {
        int dil = 1 << (i & 7);
        float* hout = (i & 1) ? hbuf : ha;
        layer_kernel<<<grid, NTHR, SMEM_BYTES>>>(hin, hout,
            Wd + i*64*32*2, bd + i*64, W1 + i*1024, b1 + i*32, dil);
        hin = hout;
    }
    // NBLK=24 even -> final h is in g_hb

    pool_kernel<<<dim3(32, B_), NTHR>>>(hbuf, hi, Wf, bf, pp);
    fc_kernel<<<B_, 64>>>(pp, fW1, fb1, fW2, fb2, out);
}

// round 10
// speedup vs baseline: 1.1583x; 1.0216x over previous
#include <cuda_runtime.h>

#define B_    16
#define L_    8192
#define CH_   32
#define NBLK  24
#define TILE  128
#define PSTR  132     // row stride ≡ 4 (mod 32), 16B aligned
#define NTHR  256

typedef unsigned long long u64;

// Scratch (device globals: allocation-free per harness rules)
__device__ float g_hi[B_*L_*CH_];    // init conv output (skip_sum = h_fin - h_init)
__device__ float g_ha[B_*L_*CH_];
__device__ float g_hb[B_*L_*CH_];
__device__ float g_pp[B_*128*8];     // pool partial maxes

// ---- packed f32x2 helpers (FFMA2 is PTX-only; ptxas won't auto-fuse) ------
__device__ __forceinline__ u64 pack2(float a, float b) {
    u64 r; asm("mov.b64 %0, {%1,%2};" : "=l"(r) : "f"(a), "f"(b)); return r;
}
__device__ __forceinline__ void unpack2(u64 v, float& a, float& b) {
    asm("mov.b64 {%0,%1}, %2;" : "=f"(a), "=f"(b) : "l"(v));
}
__device__ __forceinline__ void fma2(u64& d, u64 a, u64 b) {
    asm("fma.rn.f32x2 %0, %1, %2, %0;" : "+l"(d) : "l"(a), "l"(b));
}

// gated = tanh(f)*sigmoid(g) = (A-1)B / ((A+1)(B+1)), A=e^{2f}, B=e^{g}
// 3 MUFU (2x EX2 + 1x RCP) instead of 4.
__device__ __forceinline__ float gate(float f, float g) {
    float A = __expf(2.f*f);
    float Bv = __expf(g);
    return __fdividef((A - 1.f)*Bv, (A + 1.f)*(Bv + 1.f));
}

// Channel-pair packed weights: FFMA2 weight operands come straight from LDS.
struct __align__(16) Smem {
    // wq[c][j]: j<16 -> f-pair j = channels (2j,2j+1); j>=16 -> g-pair (j-16).
    // float4 = (tap0[lo], tap0[hi], tap1[lo], tap1[hi]); as ulonglong2:
    // .x = tap0 packed pair, .y = tap1 packed pair.
    float4 wq[32][33];
    // w1q[c][og] = (W1[2og][c], W1[2og+1][c], W1[2og+16][c], W1[2og+17][c])
    float4 w1q[32][8];
    float  bdf[32], bdg[32], b1s[32];
    float  hTc[32][PSTR];   // [c][pos]
    float  hTpg[32][PSTR];  // h[pos-dil] during conv, then reused for gated
};
#define SMEM_BYTES ((int)sizeof(Smem))

// ---------------------------------------------------------------------------
// Initial causal conv (K=2, dil=1): x (B,L) -> h_init (B,L,32)
// ---------------------------------------------------------------------------
__global__ void init_kernel(const float* __restrict__ x,
                            const float* __restrict__ W0,
                            const float* __restrict__ b0) {
    int idx = blockIdx.x * blockDim.x + threadIdx.x;
    if (idx >= B_*L_*CH_) return;
    int c = idx & 31;
    int l = (idx >> 5) & (L_ - 1);
    int b = idx >> 18;
    float xv = x[b*L_ + l];
    float xp = (l > 0) ? x[b*L_ + l - 1] : 0.f;
    g_hi[idx] = fmaf(W0[c*2 + 0], xp, fmaf(W0[c*2 + 1], xv, b0[c]));
}

// ---------------------------------------------------------------------------
// One WaveNet residual block. Thread tile: channel-pairs {2og,2og+1} and
// {2og+16,2og+17} (f and g) x 4 positions. FFMA2 packed over channel pairs.
// PDL: weights staged BEFORE the grid dependency sync (overlaps prior layer).
// ---------------------------------------------------------------------------
__global__ void __launch_bounds__(NTHR, 4) layer_kernel(
    const float* __restrict__ h_in, float* __restrict__ h_out,
    const float* __restrict__ Wd, const float* __restrict__ bd,
    const float* __restrict__ W1, const float* __restrict__ b1,
    int dil)
{
    extern __shared__ char smem_raw[];
    Smem& S = *reinterpret_cast<Smem*>(smem_raw);

    const int tid = threadIdx.x;
    const int b  = blockIdx.y;
    const int l0 = blockIdx.x * TILE;
    const int base = (b*L_ + l0) * CH_;

    // ---- stage conv weights as channel-pair float4s (independent of h_in)
    const float2* Wd2 = (const float2*)Wd;    // Wd[o][c][2] -> float2 taps
    #pragma unroll
    for (int i = tid; i < 1024; i += NTHR) {
        int j = i >> 5, c = i & 31;
        int o0 = 2*(j & 15) + ((j >= 16) ? 32 : 0);
        float2 wa = Wd2[o0*32 + c];
        float2 wb = Wd2[(o0+1)*32 + c];
        S.wq[c][j] = make_float4(wa.x, wb.x, wa.y, wb.y);
    }
    {   // skip weights, channel-pair packed (256 threads exactly)
        int og = tid & 7, c = tid >> 3;
        S.w1q[c][og] = make_float4(W1[(2*og   )*32 + c], W1[(2*og+ 1)*32 + c],
                                   W1[(2*og+16)*32 + c], W1[(2*og+17)*32 + c]);
    }
    if (tid < 32) { S.bdf[tid] = bd[tid]; S.bdg[tid] = bd[32 + tid]; S.b1s[tid] = b1[tid]; }

    // ---- wait for producer layer's h writes, then stage h tiles
    cudaGridDependencySynchronize();

    const float* hb = h_in + b*L_*CH_;
    #pragma unroll
    for (int i = tid; i < 1024; i += NTHR) {
        int c = i & 31, lq = (i >> 5) << 2;
        int gi = base + lq*CH_ + c;
        float4 vc;
        vc.x = h_in[gi]; vc.y = h_in[gi+32]; vc.z = h_in[gi+64]; vc.w = h_in[gi+96];
        *(float4*)&S.hTc[c][lq] = vc;
        int lp = l0 + lq - dil;
        float4 vp;
        vp.x = (lp   >= 0) ? hb[(lp  )*CH_ + c] : 0.f;
        vp.y = (lp+1 >= 0) ? hb[(lp+1)*CH_ + c] : 0.f;
        vp.z = (lp+2 >= 0) ? hb[(lp+2)*CH_ + c] : 0.f;
        vp.w = (lp+3 >= 0) ? hb[(lp+3)*CH_ + c] : 0.f;
        *(float4*)&S.hTpg[c][lq] = vp;
    }
    __syncthreads();

    const int w   = tid >> 5;
    const int og  = (tid >> 2) & 7;     // channel-pair group
    const int pg  = tid & 3;            // position group
    const int pb4 = w*16 + 4*pg;        // this thread's 4 positions

    // ---- dilated conv: acc = packed channel-pair, per position
    u64 accfA[4], accfB[4], accgA[4], accgB[4];
    {
        u64 bfA = *(const u64*)&S.bdf[2*og], bfB = *(const u64*)&S.bdf[2*og+16];
        u64 bgA = *(const u64*)&S.bdg[2*og], bgB = *(const u64*)&S.bdg[2*og+16];
        #pragma unroll
        for (int k = 0; k < 4; k++) {
            accfA[k] = bfA; accfB[k] = bfB; accgA[k] = bgA; accgB[k] = bgB;
        }
    }
    #pragma unroll 4
    for (int c = 0; c < 32; c++) {
        float4 hp4 = *(const float4*)&S.hTpg[c][pb4];
        float4 hc4 = *(const float4*)&S.hTc[c][pb4];
        u64 dp[4], dc[4];
        dp[0] = pack2(hp4.x, hp4.x); dp[1] = pack2(hp4.y, hp4.y);
        dp[2] = pack2(hp4.z, hp4.z); dp[3] = pack2(hp4.w, hp4.w);
        dc[0] = pack2(hc4.x, hc4.x); dc[1] = pack2(hc4.y, hc4.y);
        dc[2] = pack2(hc4.z, hc4.z); dc[3] = pack2(hc4.w, hc4.w);
        ulonglong2 wfA = *(const ulonglong2*)&S.wq[c][og];
        #pragma unroll
        for (int k = 0; k < 4; k++) { fma2(accfA[k], wfA.x, dp[k]); fma2(accfA[k], wfA.y, dc[k]); }
        ulonglong2 wfB = *(const ulonglong2*)&S.wq[c][og + 8];
        #pragma unroll
        for (int k = 0; k < 4; k++) { fma2(accfB[k], wfB.x, dp[k]); fma2(accfB[k], wfB.y, dc[k]); }
        ulonglong2 wgA = *(const ulonglong2*)&S.wq[c][16 + og];
        #pragma unroll
        for (int k = 0; k < 4; k++) { fma2(accgA[k], wgA.x, dp[k]); fma2(accgA[k], wgA.y, dc[k]); }
        ulonglong2 wgB = *(const ulonglong2*)&S.wq[c][24 + og];
        #pragma unroll
        for (int k = 0; k < 4; k++) { fma2(accgB[k], wgB.x, dp[k]); fma2(accgB[k], wgB.y, dc[k]); }
    }

    // ---- gating: tanh(f)*sigmoid(g); write gated rows into hTpg (reuse).
    __syncwarp();
    {
        float rA0[4], rA1[4], rB0[4], rB1[4];
        #pragma unroll
        for (int k = 0; k < 4; k++) {
            float fa0, fa1, ga0, ga1, fb0, fb1, gb0, gb1;
            unpack2(accfA[k], fa0, fa1); unpack2(accgA[k], ga0, ga1);
            unpack2(accfB[k], fb0, fb1); unpack2(accgB[k], gb0, gb1);
            rA0[k] = gate(fa0, ga0); rA1[k] = gate(fa1, ga1);
            rB0[k] = gate(fb0, gb0); rB1[k] = gate(fb1, gb1);
        }
        *(float4*)&S.hTpg[2*og   ][pb4] = make_float4(rA0[0], rA0[1], rA0[2], rA0[3]);
        *(float4*)&S.hTpg[2*og+ 1][pb4] = make_float4(rA1[0], rA1[1], rA1[2], rA1[3]);
        *(float4*)&S.hTpg[2*og+16][pb4] = make_float4(rB0[0], rB0[1], rB0[2], rB0[3]);
        *(float4*)&S.hTpg[2*og+17][pb4] = make_float4(rB1[0], rB1[1], rB1[2], rB1[3]);
    }
    __syncwarp();   // gated columns [w*16, w*16+16) are entirely warp-local

    // ---- skip = W1 @ gated + b1 (channel-pair packed; weights direct from LDS)
    u64 accsA[4], accsB[4];
    {
        u64 bsA = *(const u64*)&S.b1s[2*og], bsB = *(const u64*)&S.b1s[2*og+16];
        #pragma unroll
        for (int k = 0; k < 4; k++) { accsA[k] = bsA; accsB[k] = bsB; }
    }
    #pragma unroll 4
    for (int c = 0; c < 32; c++) {
        float4 gg = *(const float4*)&S.hTpg[c][pb4];
        u64 d0 = pack2(gg.x, gg.x), d1 = pack2(gg.y, gg.y);
        u64 d2 = pack2(gg.z, gg.z), d3 = pack2(gg.w, gg.w);
        ulonglong2 wp = *(const ulonglong2*)&S.w1q[c][og];
        fma2(accsA[0], wp.x, d0); fma2(accsB[0], wp.y, d0);
        fma2(accsA[1], wp.x, d1); fma2(accsB[1], wp.y, d1);
        fma2(accsA[2], wp.x, d2); fma2(accsB[2], wp.y, d2);
        fma2(accsA[3], wp.x, d3); fma2(accsB[3], wp.y, d3);
    }

    // ---- residual: h_out = h_in + skip; adjacent channel pairs -> STG.64
    {
        float4 h0 = *(const float4*)&S.hTc[2*og   ][pb4];
        float4 h1 = *(const float4*)&S.hTc[2*og+ 1][pb4];
        float4 h2 = *(const float4*)&S.hTc[2*og+16][pb4];
        float4 h3 = *(const float4*)&S.hTc[2*og+17][pb4];
        float h0a[4] = {h0.x,h0.y,h0.z,h0.w}, h1a[4] = {h1.x,h1.y,h1.z,h1.w};
        float h2a[4] = {h2.x,h2.y,h2.z,h2.w}, h3a[4] = {h3.x,h3.y,h3.z,h3.w};
        #pragma unroll
        for (int k = 0; k < 4; k++) {
            float sa0, sa1, sb0, sb1;
            unpack2(accsA[k], sa0, sa1);
            unpack2(accsB[k], sb0, sb1);
            int gi = base + (pb4 + k)*CH_;
            *(float2*)&h_out[gi + 2*og]      = make_float2(h0a[k] + sa0, h1a[k] + sa1);
            *(float2*)&h_out[gi + 2*og + 16] = make_float2(h2a[k] + sb0, h3a[k] + sb1);
        }
    }
    // Let the next layer's grid launch as soon as all CTAs reach here.
    cudaTriggerProgrammaticLaunchCompletion();
}

// ---------------------------------------------------------------------------
// pool: skip_sum = h_fin - h_init; y = relu(Wf@relu(skip)+bf) max-pooled.
// PDL: Wf staging overlaps the last layer.
// ---------------------------------------------------------------------------
__global__ __launch_bounds__(NTHR) void pool_kernel(
    const float* __restrict__ h_fin, const float* __restrict__ h_init,
    const float* __restrict__ Wf, const float* __restrict__ bf,
    float* __restrict__ pp)
{
    __shared__ float wfT[32][33];
    __shared__ float bfs[32];
    __shared__ float pmax[8][32];
    const int tid = threadIdx.x;
    const int q = blockIdx.x >> 3, s = blockIdx.x & 7;
    const int b = blockIdx.y;

    for (int i = tid; i < 1024; i += NTHR) wfT[i & 31][i >> 5] = Wf[i];
    if (tid < 32) bfs[tid] = bf[tid];
    cudaGridDependencySynchronize();
    __syncthreads();

    const int w = tid >> 5, o = tid & 31;
    const int lbase = q * (L_/4) + s * (L_/32);
    float m = 0.f;   // relu folded into max
    for (int p = w; p < L_/32; p += 8) {
        int gi = (b*L_ + lbase + p)*CH_ + o;
        float sv = fmaxf(h_fin[gi] - h_init[gi], 0.f);
        float acc = bfs[o];
        #pragma unroll
        for (int c = 0; c < 32; c++)
            acc = fmaf(wfT[c][o], __shfl_sync(0xffffffffu, sv, c), acc);
        m = fmaxf(m, acc);
    }
    pmax[w][o] = m;
    __syncthreads();
    if (w == 0) {
        float mm = pmax[0][o];
        #pragma unroll
        for (int k = 1; k < 8; k++) mm = fmaxf(mm, pmax[k][o]);
        pp[b*1024 + (o*4 + q)*8 + s] = mm;   // feature index = c*4 + q
    }
}

// ---------------------------------------------------------------------------
// FC head: reduce partials, 128 -> 64 (relu) -> 10
// ---------------------------------------------------------------------------
__global__ void fc_kernel(const float* __restrict__ pp,
                          const float* __restrict__ fW1, const float* __restrict__ fb1,
                          const float* __restrict__ fW2, const float* __restrict__ fb2,
                          float* __restrict__ out)
{
    __shared__ float ps[128], h1[64];
    const int b = blockIdx.x, tid = threadIdx.x;
    #pragma unroll
    for (int f = tid; f < 128; f += 64) {
        const float* p = pp + b*1024 + f*8;
        float m = p[0];
        #pragma unroll
        for (int k = 1; k < 8; k++) m = fmaxf(m, p[k]);
        ps[f] = m;
    }
    __syncthreads();
    float acc = fb1[tid];
    #pragma unroll 8
    for (int k = 0; k < 128; k++) acc = fmaf(fW1[tid*128 + k], ps[k], acc);
    h1[tid] = fmaxf(acc, 0.f);
    __syncthreads();
    if (tid < 10) {
        float a2 = fb2[tid];
        #pragma unroll 8
        for (int k = 0; k < 64; k++) a2 = fmaf(fW2[tid*64 + k], h1[k], a2);
        out[b*10 + tid] = a2;
    }
}

// ---------------------------------------------------------------------------
extern "C" void kernel_launch(void* const* d_in, const int* in_sizes, int n_in,
                              void* d_out, int out_size)
{
    const float* x   = (const float*)d_in[0];
    const float* W0  = (const float*)d_in[1];
    const float* b0  = (const float*)d_in[2];
    const float* Wd  = (const float*)d_in[3];   // (24, 64, 32, 2)
    const float* bd  = (const float*)d_in[4];   // (24, 64)
    const float* W1  = (const float*)d_in[5];   // (24, 32, 32)
    const float* b1  = (const float*)d_in[6];   // (24, 32)
    const float* Wf  = (const float*)d_in[7];
    const float* bf  = (const float*)d_in[8];
    const float* fW1 = (const float*)d_in[9];
    const float* fb1 = (const float*)d_in[10];
    const float* fW2 = (const float*)d_in[11];
    const float* fb2 = (const float*)d_in[12];
    float* out = (float*)d_out;

    static bool attr_done = false;
    if (!attr_done) {
        cudaFuncSetAttribute(layer_kernel,
            cudaFuncAttributeMaxDynamicSharedMemorySize, SMEM_BYTES);
        attr_done = true;
    }

    float *hi, *ha, *hbuf, *pp;
    cudaGetSymbolAddress((void**)&hi,   g_hi);
    cudaGetSymbolAddress((void**)&ha,   g_ha);
    cudaGetSymbolAddress((void**)&hbuf, g_hb);
    cudaGetSymbolAddress((void**)&pp,   g_pp);

    init_kernel<<<(B_*L_*CH_ + 255)/256, 256>>>(x, W0, b0);

    // PDL launch config for the layer chain + pool
    cudaLaunchAttribute pdl[1];
    pdl[0].id = cudaLaunchAttributeProgrammaticStreamSerialization;
    pdl[0].val.programmaticStreamSerializationAllowed = 1;

    cudaLaunchConfig_t cfgL = {};
    cfgL.gridDim  = dim3(L_/TILE, B_);
    cfgL.blockDim = dim3(NTHR);
    cfgL.dynamicSmemBytes = SMEM_BYTES;
    cfgL.stream = 0;
    cfgL.attrs = pdl;
    cfgL.numAttrs = 1;

    const float* hin = hi;
    for (int i = 0; i < NBLK; i++) {
        int dil = 1 << (i & 7);
        float* hout = (i & 1) ? hbuf : ha;
        cudaLaunchKernelEx(&cfgL, layer_kernel, hin, hout,
            Wd + i*64*32*2, bd + i*64, W1 + i*1024, b1 + i*32, dil);
        hin = hout;
    }
    // NBLK=24 even -> final h is in g_hb

    cudaLaunchConfig_t cfgP = {};
    cfgP.gridDim  = dim3(32, B_);
    cfgP.blockDim = dim3(NTHR);
    cfgP.dynamicSmemBytes = 0;
    cfgP.stream = 0;
    cfgP.attrs = pdl;
    cfgP.numAttrs = 1;
    cudaLaunchKernelEx(&cfgP, pool_kernel,
        (const float*)hbuf, (const float*)hi, Wf, bf, pp);

    fc_kernel<<<B_, 64>>>(pp, fW1, fb1, fW2, fb2, out);
}

// round 11
// speedup vs baseline: 1.2388x; 1.0695x over previous
#include <cuda_runtime.h>

#define B_    16
#define L_    8192
#define CH_   32
#define NBLK  24
#define TILE  128
#define PSTR  132     // row stride ≡ 4 (mod 32), 16B aligned
#define NTHR  256
#define NTILE 1024    // tiles per layer = (L_/TILE) * B_

typedef unsigned long long u64;

// Scratch (device globals: allocation-free per harness rules)
__device__ float g_hi[B_*L_*CH_];    // init conv output (skip_sum = h_fin - h_init)
__device__ float g_ha[B_*L_*CH_];
__device__ float g_hb[B_*L_*CH_];
__device__ float g_pp[B_*128*8];     // pool partial maxes
__device__ int   g_flags[NBLK*NTILE];// cross-layer completion flags

// ---- packed f32x2 helpers (FFMA2 is PTX-only; ptxas won't auto-fuse) ------
__device__ __forceinline__ u64 pack2(float a, float b) {
    u64 r; asm("mov.b64 %0, {%1,%2};" : "=l"(r) : "f"(a), "f"(b)); return r;
}
__device__ __forceinline__ void unpack2(u64 v, float& a, float& b) {
    asm("mov.b64 {%0,%1}, %2;" : "=f"(a), "=f"(b) : "l"(v));
}
__device__ __forceinline__ void fma2(u64& d, u64 a, u64 b) {
    asm("fma.rn.f32x2 %0, %1, %2, %0;" : "+l"(d) : "l"(a), "l"(b));
}

// gated = tanh(f)*sigmoid(g) = (A-1)B / ((A+1)(B+1)), A=e^{2f}, B=e^{g}
__device__ __forceinline__ float gate(float f, float g) {
    float A = __expf(2.f*f);
    float Bv = __expf(g);
    return __fdividef((A - 1.f)*Bv, (A + 1.f)*(Bv + 1.f));
}

// Channel-pair packed weights: FFMA2 weight operands come straight from LDS.
struct __align__(16) Smem {
    float4 wq[32][33];
    float4 w1q[32][8];
    float  bdf[32], bdg[32], b1s[32];
    float  hTc[32][PSTR];   // [c][pos]
    float  hTpg[32][PSTR];  // h[pos-dil] during conv, then reused for gated
};
#define SMEM_BYTES ((int)sizeof(Smem))

// ---------------------------------------------------------------------------
// Initial causal conv (K=2, dil=1): x (B,L) -> h_init; also zero flags.
// ---------------------------------------------------------------------------
__global__ void init_kernel(const float* __restrict__ x,
                            const float* __restrict__ W0,
                            const float* __restrict__ b0) {
    int idx = blockIdx.x * blockDim.x + threadIdx.x;
    if (idx < NBLK*NTILE) g_flags[idx] = 0;
    if (idx >= B_*L_*CH_) return;
    int c = idx & 31;
    int l = (idx >> 5) & (L_ - 1);
    int b = idx >> 18;
    float xv = x[b*L_ + l];
    float xp = (l > 0) ? x[b*L_ + l - 1] : 0.f;
    g_hi[idx] = fmaf(W0[c*2 + 0], xp, fmaf(W0[c*2 + 1], xv, b0[c]));
}

// ---------------------------------------------------------------------------
// ALL 24 residual blocks in one persistent grid; cross-layer dependencies via
// per-tile flags (layer i+1 tile t needs layer i tiles t and t-1: dil<=TILE).
// CTA order: bid = layer*NTILE + tile -> dependency distance >= 1023 > resident
// window (~592 CTAs), and CTAs dispatch in monotone bid order => no deadlock,
// near-zero spin, fully pipelined layer wavefront.
// ---------------------------------------------------------------------------
__global__ void __launch_bounds__(NTHR, 4) chain_kernel(
    const float* __restrict__ WdAll, const float* __restrict__ bdAll,
    const float* __restrict__ W1All, const float* __restrict__ b1All)
{
    extern __shared__ char smem_raw[];
    Smem& S = *reinterpret_cast<Smem*>(smem_raw);

    const int tid  = threadIdx.x;
    const int bid  = blockIdx.x;
    const int i    = bid >> 10;          // layer
    const int tile = bid & (NTILE - 1);
    const int b    = tile >> 6;
    const int tt   = tile & 63;
    const int l0   = tt * TILE;
    const int dil  = 1 << (i & 7);
    const int base = (b*L_ + l0) * CH_;

    const float* Wd = WdAll + i*64*32*2;
    const float* bd = bdAll + i*64;
    const float* W1 = W1All + i*1024;
    const float* b1 = b1All + i*32;
    const float* h_in = (i == 0) ? g_hi : ((i & 1) ? g_ha : g_hb);
    float*       h_out = (i & 1) ? g_hb : g_ha;

    // ---- stage weights first (independent of producer layer)
    const float2* Wd2 = (const float2*)Wd;
    #pragma unroll
    for (int idx = tid; idx < 1024; idx += NTHR) {
        int j = idx >> 5, c = idx & 31;
        int o0 = 2*(j & 15) + ((j >= 16) ? 32 : 0);
        float2 wa = Wd2[o0*32 + c];
        float2 wb = Wd2[(o0+1)*32 + c];
        S.wq[c][j] = make_float4(wa.x, wb.x, wa.y, wb.y);
    }
    {
        int og = tid & 7, c = tid >> 3;
        S.w1q[c][og] = make_float4(W1[(2*og   )*32 + c], W1[(2*og+ 1)*32 + c],
                                   W1[(2*og+16)*32 + c], W1[(2*og+17)*32 + c]);
    }
    if (tid < 32) { S.bdf[tid] = bd[tid]; S.bdg[tid] = bd[32 + tid]; S.b1s[tid] = b1[tid]; }

    // ---- wait for producer tiles (decoupled-lookback pattern)
    if (i > 0 && tid == 0) {
        int fidx = (i-1)*NTILE + tile;
        while (atomicAdd(&g_flags[fidx], 0) == 0) __nanosleep(64);
        if (tt > 0)
            while (atomicAdd(&g_flags[fidx - 1], 0) == 0) __nanosleep(64);
        __threadfence();
    }
    __syncthreads();

    // ---- stage h tiles transposed to [c][pos]
    const float* hb = h_in + b*L_*CH_;
    #pragma unroll
    for (int idx = tid; idx < 1024; idx += NTHR) {
        int c = idx & 31, lq = (idx >> 5) << 2;
        int gi = base + lq*CH_ + c;
        float4 vc;
        vc.x = h_in[gi]; vc.y = h_in[gi+32]; vc.z = h_in[gi+64]; vc.w = h_in[gi+96];
        *(float4*)&S.hTc[c][lq] = vc;
        int lp = l0 + lq - dil;
        float4 vp;
        vp.x = (lp   >= 0) ? hb[(lp  )*CH_ + c] : 0.f;
        vp.y = (lp+1 >= 0) ? hb[(lp+1)*CH_ + c] : 0.f;
        vp.z = (lp+2 >= 0) ? hb[(lp+2)*CH_ + c] : 0.f;
        vp.w = (lp+3 >= 0) ? hb[(lp+3)*CH_ + c] : 0.f;
        *(float4*)&S.hTpg[c][lq] = vp;
    }
    __syncthreads();

    const int w   = tid >> 5;
    const int og  = (tid >> 2) & 7;     // channel-pair group
    const int pg  = tid & 3;            // position group
    const int pb4 = w*16 + 4*pg;        // this thread's 4 positions

    // ---- dilated conv: acc = packed channel-pair, per position
    u64 accfA[4], accfB[4], accgA[4], accgB[4];
    {
        u64 bfA = *(const u64*)&S.bdf[2*og], bfB = *(const u64*)&S.bdf[2*og+16];
        u64 bgA = *(const u64*)&S.bdg[2*og], bgB = *(const u64*)&S.bdg[2*og+16];
        #pragma unroll
        for (int k = 0; k < 4; k++) {
            accfA[k] = bfA; accfB[k] = bfB; accgA[k] = bgA; accgB[k] = bgB;
        }
    }
    #pragma unroll 4
    for (int c = 0; c < 32; c++) {
        float4 hp4 = *(const float4*)&S.hTpg[c][pb4];
        float4 hc4 = *(const float4*)&S.hTc[c][pb4];
        u64 dp[4], dc[4];
        dp[0] = pack2(hp4.x, hp4.x); dp[1] = pack2(hp4.y, hp4.y);
        dp[2] = pack2(hp4.z, hp4.z); dp[3] = pack2(hp4.w, hp4.w);
        dc[0] = pack2(hc4.x, hc4.x); dc[1] = pack2(hc4.y, hc4.y);
        dc[2] = pack2(hc4.z, hc4.z); dc[3] = pack2(hc4.w, hc4.w);
        ulonglong2 wfA = *(const ulonglong2*)&S.wq[c][og];
        #pragma unroll
        for (int k = 0; k < 4; k++) { fma2(accfA[k], wfA.x, dp[k]); fma2(accfA[k], wfA.y, dc[k]); }
        ulonglong2 wfB = *(const ulonglong2*)&S.wq[c][og + 8];
        #pragma unroll
        for (int k = 0; k < 4; k++) { fma2(accfB[k], wfB.x, dp[k]); fma2(accfB[k], wfB.y, dc[k]); }
        ulonglong2 wgA = *(const ulonglong2*)&S.wq[c][16 + og];
        #pragma unroll
        for (int k = 0; k < 4; k++) { fma2(accgA[k], wgA.x, dp[k]); fma2(accgA[k], wgA.y, dc[k]); }
        ulonglong2 wgB = *(const ulonglong2*)&S.wq[c][24 + og];
        #pragma unroll
        for (int k = 0; k < 4; k++) { fma2(accgB[k], wgB.x, dp[k]); fma2(accgB[k], wgB.y, dc[k]); }
    }

    // ---- gating; write gated rows into hTpg (warp-local column stripe reuse)
    __syncwarp();
    {
        float rA0[4], rA1[4], rB0[4], rB1[4];
        #pragma unroll
        for (int k = 0; k < 4; k++) {
            float fa0, fa1, ga0, ga1, fb0, fb1, gb0, gb1;
            unpack2(accfA[k], fa0, fa1); unpack2(accgA[k], ga0, ga1);
            unpack2(accfB[k], fb0, fb1); unpack2(accgB[k], gb0, gb1);
            rA0[k] = gate(fa0, ga0); rA1[k] = gate(fa1, ga1);
            rB0[k] = gate(fb0, gb0); rB1[k] = gate(fb1, gb1);
        }
        *(float4*)&S.hTpg[2*og   ][pb4] = make_float4(rA0[0], rA0[1], rA0[2], rA0[3]);
        *(float4*)&S.hTpg[2*og+ 1][pb4] = make_float4(rA1[0], rA1[1], rA1[2], rA1[3]);
        *(float4*)&S.hTpg[2*og+16][pb4] = make_float4(rB0[0], rB0[1], rB0[2], rB0[3]);
        *(float4*)&S.hTpg[2*og+17][pb4] = make_float4(rB1[0], rB1[1], rB1[2], rB1[3]);
    }
    __syncwarp();

    // ---- skip = W1 @ gated + b1
    u64 accsA[4], accsB[4];
    {
        u64 bsA = *(const u64*)&S.b1s[2*og], bsB = *(const u64*)&S.b1s[2*og+16];
        #pragma unroll
        for (int k = 0; k < 4; k++) { accsA[k] = bsA; accsB[k] = bsB; }
    }
    #pragma unroll 4
    for (int c = 0; c < 32; c++) {
        float4 gg = *(const float4*)&S.hTpg[c][pb4];
        u64 d0 = pack2(gg.x, gg.x), d1 = pack2(gg.y, gg.y);
        u64 d2 = pack2(gg.z, gg.z), d3 = pack2(gg.w, gg.w);
        ulonglong2 wp = *(const ulonglong2*)&S.w1q[c][og];
        fma2(accsA[0], wp.x, d0); fma2(accsB[0], wp.y, d0);
        fma2(accsA[1], wp.x, d1); fma2(accsB[1], wp.y, d1);
        fma2(accsA[2], wp.x, d2); fma2(accsB[2], wp.y, d2);
        fma2(accsA[3], wp.x, d3); fma2(accsB[3], wp.y, d3);
    }

    // ---- residual: h_out = h_in + skip; adjacent channel pairs -> STG.64
    {
        float4 h0 = *(const float4*)&S.hTc[2*og   ][pb4];
        float4 h1 = *(const float4*)&S.hTc[2*og+ 1][pb4];
        float4 h2 = *(const float4*)&S.hTc[2*og+16][pb4];
        float4 h3 = *(const float4*)&S.hTc[2*og+17][pb4];
        float h0a[4] = {h0.x,h0.y,h0.z,h0.w}, h1a[4] = {h1.x,h1.y,h1.z,h1.w};
        float h2a[4] = {h2.x,h2.y,h2.z,h2.w}, h3a[4] = {h3.x,h3.y,h3.z,h3.w};
        #pragma unroll
        for (int k = 0; k < 4; k++) {
            float sa0, sa1, sb0, sb1;
            unpack2(accsA[k], sa0, sa1);
            unpack2(accsB[k], sb0, sb1);
            int gi = base + (pb4 + k)*CH_;
            *(float2*)&h_out[gi + 2*og]      = make_float2(h0a[k] + sa0, h1a[k] + sa1);
            *(float2*)&h_out[gi + 2*og + 16] = make_float2(h2a[k] + sb0, h3a[k] + sb1);
        }
    }

    // ---- publish this tile's completion
    __syncthreads();
    if (tid == 0) {
        __threadfence();
        atomicExch(&g_flags[i*NTILE + tile], 1);
    }
}

// ---------------------------------------------------------------------------
// pool: skip_sum = h_fin - h_init; y = relu(Wf@relu(skip)+bf) max-pooled.
// PDL: Wf staging overlaps the chain kernel's tail.
// ---------------------------------------------------------------------------
__global__ __launch_bounds__(NTHR) void pool_kernel(
    const float* __restrict__ h_fin, const float* __restrict__ h_init,
    const float* __restrict__ Wf, const float* __restrict__ bf,
    float* __restrict__ pp)
{
    __shared__ float wfT[32][33];
    __shared__ float bfs[32];
    __shared__ float pmax[8][32];
    const int tid = threadIdx.x;
    const int q = blockIdx.x >> 3, s = blockIdx.x & 7;
    const int b = blockIdx.y;

    for (int i = tid; i < 1024; i += NTHR) wfT[i & 31][i >> 5] = Wf[i];
    if (tid < 32) bfs[tid] = bf[tid];
    cudaGridDependencySynchronize();
    __syncthreads();

    const int w = tid >> 5, o = tid & 31;
    const int lbase = q * (L_/4) + s * (L_/32);
    float m = 0.f;   // relu folded into max
    for (int p = w; p < L_/32; p += 8) {
        int gi = (b*L_ + lbase + p)*CH_ + o;
        float sv = fmaxf(h_fin[gi] - h_init[gi], 0.f);
        float acc = bfs[o];
        #pragma unroll
        for (int c = 0; c < 32; c++)
            acc = fmaf(wfT[c][o], __shfl_sync(0xffffffffu, sv, c), acc);
        m = fmaxf(m, acc);
    }
    pmax[w][o] = m;
    __syncthreads();
    if (w == 0) {
        float mm = pmax[0][o];
        #pragma unroll
        for (int k = 1; k < 8; k++) mm = fmaxf(mm, pmax[k][o]);
        pp[b*1024 + (o*4 + q)*8 + s] = mm;   // feature index = c*4 + q
    }
}

// ---------------------------------------------------------------------------
// FC head: reduce partials, 128 -> 64 (relu) -> 10
// ---------------------------------------------------------------------------
__global__ void fc_kernel(const float* __restrict__ pp,
                          const float* __restrict__ fW1, const float* __restrict__ fb1,
                          const float* __restrict__ fW2, const float* __restrict__ fb2,
                          float* __restrict__ out)
{
    __shared__ float ps[128], h1[64];
    const int b = blockIdx.x, tid = threadIdx.x;
    #pragma unroll
    for (int f = tid; f < 128; f += 64) {
        const float* p = pp + b*1024 + f*8;
        float m = p[0];
        #pragma unroll
        for (int k = 1; k < 8; k++) m = fmaxf(m, p[k]);
        ps[f] = m;
    }
    __syncthreads();
    float acc = fb1[tid];
    #pragma unroll 8
    for (int k = 0; k < 128; k++) acc = fmaf(fW1[tid*128 + k], ps[k], acc);
    h1[tid] = fmaxf(acc, 0.f);
    __syncthreads();
    if (tid < 10) {
        float a2 = fb2[tid];
        #pragma unroll 8
        for (int k = 0; k < 64; k++) a2 = fmaf(fW2[tid*64 + k], h1[k], a2);
        out[b*10 + tid] = a2;
    }
}

// ---------------------------------------------------------------------------
extern "C" void kernel_launch(void* const* d_in, const int* in_sizes, int n_in,
                              void* d_out, int out_size)
{
    const float* x   = (const float*)d_in[0];
    const float* W0  = (const float*)d_in[1];
    const float* b0  = (const float*)d_in[2];
    const float* Wd  = (const float*)d_in[3];   // (24, 64, 32, 2)
    const float* bd  = (const float*)d_in[4];   // (24, 64)
    const float* W1  = (const float*)d_in[5];   // (24, 32, 32)
    const float* b1  = (const float*)d_in[6];   // (24, 32)
    const float* Wf  = (const float*)d_in[7];
    const float* bf  = (const float*)d_in[8];
    const float* fW1 = (const float*)d_in[9];
    const float* fb1 = (const float*)d_in[10];
    const float* fW2 = (const float*)d_in[11];
    const float* fb2 = (const float*)d_in[12];
    float* out = (float*)d_out;

    static bool attr_done = false;
    if (!attr_done) {
        cudaFuncSetAttribute(chain_kernel,
            cudaFuncAttributeMaxDynamicSharedMemorySize, SMEM_BYTES);
        attr_done = true;
    }

    float *hi, *hbuf, *pp;
    cudaGetSymbolAddress((void**)&hi,   g_hi);
    cudaGetSymbolAddress((void**)&hbuf, g_hb);
    cudaGetSymbolAddress((void**)&pp,   g_pp);

    init_kernel<<<(B_*L_*CH_ + 255)/256, 256>>>(x, W0, b0);

    // All 24 layers, one persistent flag-chained grid
    chain_kernel<<<NBLK*NTILE, NTHR, SMEM_BYTES>>>(Wd, bd, W1, b1);
    // NBLK=24 even -> final h is in g_hb

    cudaLaunchAttribute pdl[1];
    pdl[0].id = cudaLaunchAttributeProgrammaticStreamSerialization;
    pdl[0].val.programmaticStreamSerializationAllowed = 1;
    cudaLaunchConfig_t cfgP = {};
    cfgP.gridDim  = dim3(32, B_);
    cfgP.blockDim = dim3(NTHR);
    cfgP.dynamicSmemBytes = 0;
    cfgP.stream = 0;
    cfgP.attrs = pdl;
    cfgP.numAttrs = 1;
    cudaLaunchKernelEx(&cfgP, pool_kernel,
        (const float*)hbuf, (const float*)hi, Wf, bf, pp);

    fc_kernel<<<B_, 64>>>(pp, fW1, fb1, fW2, fb2, out);
}

// round 12
// speedup vs baseline: 1.2717x; 1.0266x over previous
#include <cuda_runtime.h>

#define B_    16
#define L_    8192
#define CH_   32
#define NBLK  24
#define TILE  128
#define PSTR  132     // row stride ≡ 4 (mod 32), 16B aligned
#define NTHR  256
#define NTILE 1024    // tiles per layer = (L_/TILE) * B_
#define NGRID ((NBLK+1)*NTILE)   // +1 pool "layer"

typedef unsigned long long u64;

// Scratch (device globals: allocation-free per harness rules)
__device__ float g_hi[B_*L_*CH_];    // init conv output (skip_sum = h_fin - h_init)
__device__ float g_ha[B_*L_*CH_];
__device__ float g_hb[B_*L_*CH_];
__device__ float g_pool[B_*128];     // pooled features (atomicMax-accumulated)
__device__ int   g_flags[NBLK*NTILE];// cross-layer completion flags

// ---- packed f32x2 helpers (FFMA2 is PTX-only; ptxas won't auto-fuse) ------
__device__ __forceinline__ u64 pack2(float a, float b) {
    u64 r; asm("mov.b64 %0, {%1,%2};" : "=l"(r) : "f"(a), "f"(b)); return r;
}
__device__ __forceinline__ void unpack2(u64 v, float& a, float& b) {
    asm("mov.b64 {%0,%1}, %2;" : "=f"(a), "=f"(b) : "l"(v));
}
__device__ __forceinline__ void fma2(u64& d, u64 a, u64 b) {
    asm("fma.rn.f32x2 %0, %1, %2, %0;" : "+l"(d) : "l"(a), "l"(b));
}

// gated = tanh(f)*sigmoid(g) = (A-1)B / ((A+1)(B+1)), A=e^{2f}, B=e^{g}
__device__ __forceinline__ float gate(float f, float g) {
    float A = __expf(2.f*f);
    float Bv = __expf(g);
    return __fdividef((A - 1.f)*Bv, (A + 1.f)*(Bv + 1.f));
}

// Channel-pair packed weights: FFMA2 weight operands come straight from LDS.
struct __align__(16) Smem {
    float4 wq[32][33];
    float4 w1q[32][8];
    float  bdf[32], bdg[32], b1s[32];
    float  hTc[32][PSTR];   // [c][pos]
    float  hTpg[32][PSTR];  // h[pos-dil] during conv, then reused for gated
};
#define SMEM_BYTES ((int)sizeof(Smem))

// ---------------------------------------------------------------------------
// Initial causal conv (K=2, dil=1): x (B,L) -> h_init; zero flags + pool.
// ---------------------------------------------------------------------------
__global__ void init_kernel(const float* __restrict__ x,
                            const float* __restrict__ W0,
                            const float* __restrict__ b0) {
    int idx = blockIdx.x * blockDim.x + threadIdx.x;
    if (idx < NBLK*NTILE) g_flags[idx] = 0;
    if (idx < B_*128)     g_pool[idx]  = 0.f;
    if (idx >= B_*L_*CH_) return;
    int c = idx & 31;
    int l = (idx >> 5) & (L_ - 1);
    int b = idx >> 18;
    float xv = x[b*L_ + l];
    float xp = (l > 0) ? x[b*L_ + l - 1] : 0.f;
    g_hi[idx] = fmaf(W0[c*2 + 0], xp, fmaf(W0[c*2 + 1], xv, b0[c]));
}

// ---------------------------------------------------------------------------
// 24 residual blocks + fused pool, one persistent flag-chained grid.
// bid = layer*NTILE + tile; layer NBLK = pool pass (waits on layer 23 flags).
// Dependency distance >= 1023 > resident window => monotone dispatch keeps it
// deadlock-free with near-zero spin.
// ---------------------------------------------------------------------------
__global__ void __launch_bounds__(NTHR, 4) chain_kernel(
    const float* __restrict__ WdAll, const float* __restrict__ bdAll,
    const float* __restrict__ W1All, const float* __restrict__ b1All,
    const float* __restrict__ Wf,    const float* __restrict__ bf)
{
    extern __shared__ char smem_raw[];
    Smem& S = *reinterpret_cast<Smem*>(smem_raw);

    const int tid  = threadIdx.x;
    const int bid  = blockIdx.x;
    const int i    = bid >> 10;          // layer (NBLK = pool pass)
    const int tile = bid & (NTILE - 1);
    const int b    = tile >> 6;
    const int tt   = tile & 63;
    const int l0   = tt * TILE;
    const int base = (b*L_ + l0) * CH_;

    const int w   = tid >> 5;
    const int og  = (tid >> 2) & 7;     // channel-pair group
    const int pg  = tid & 3;            // position group
    const int pb4 = w*16 + 4*pg;        // this thread's 4 positions

    // ======================= POOL PASS (i == NBLK) =========================
    if (i == NBLK) {
        // stage Wf packed (independent of producers)
        {
            int og_ = tid & 7, c = tid >> 3;
            S.w1q[c][og_] = make_float4(Wf[(2*og_   )*32 + c], Wf[(2*og_+ 1)*32 + c],
                                        Wf[(2*og_+16)*32 + c], Wf[(2*og_+17)*32 + c]);
        }
        if (tid < 32) S.b1s[tid] = bf[tid];

        if (tid == 0) {
            int fidx = (NBLK-1)*NTILE + tile;
            while (atomicAdd(&g_flags[fidx], 0) == 0) __nanosleep(64);
            __threadfence();
        }
        __syncthreads();

        // stage sv = relu(h_fin - h_init), transposed [c][pos]
        #pragma unroll
        for (int idx = tid; idx < 1024; idx += NTHR) {
            int c = idx & 31, lq = (idx >> 5) << 2;
            int gi = base + lq*CH_ + c;
            float4 v;
            v.x = fmaxf(g_hb[gi]    - g_hi[gi],    0.f);
            v.y = fmaxf(g_hb[gi+32] - g_hi[gi+32], 0.f);
            v.z = fmaxf(g_hb[gi+64] - g_hi[gi+64], 0.f);
            v.w = fmaxf(g_hb[gi+96] - g_hi[gi+96], 0.f);
            *(float4*)&S.hTc[c][lq] = v;
        }
        __syncthreads();

        // y = relu(Wf @ sv + bf), channel-pair FFMA2 matvec
        u64 accA[4], accB[4];
        {
            u64 bA = *(const u64*)&S.b1s[2*og], bB = *(const u64*)&S.b1s[2*og+16];
            #pragma unroll
            for (int k = 0; k < 4; k++) { accA[k] = bA; accB[k] = bB; }
        }
        #pragma unroll 4
        for (int c = 0; c < 32; c++) {
            float4 gg = *(const float4*)&S.hTc[c][pb4];
            u64 d0 = pack2(gg.x, gg.x), d1 = pack2(gg.y, gg.y);
            u64 d2 = pack2(gg.z, gg.z), d3 = pack2(gg.w, gg.w);
            ulonglong2 wp = *(const ulonglong2*)&S.w1q[c][og];
            fma2(accA[0], wp.x, d0); fma2(accB[0], wp.y, d0);
            fma2(accA[1], wp.x, d1); fma2(accB[1], wp.y, d1);
            fma2(accA[2], wp.x, d2); fma2(accB[2], wp.y, d2);
            fma2(accA[3], wp.x, d3); fma2(accB[3], wp.y, d3);
        }
        // relu folded into max (init 0); per-thread max over 4 positions
        float m0 = 0.f, m1 = 0.f, m2 = 0.f, m3 = 0.f;
        #pragma unroll
        for (int k = 0; k < 4; k++) {
            float a0, a1, b0v, b1v;
            unpack2(accA[k], a0, a1);
            unpack2(accB[k], b0v, b1v);
            m0 = fmaxf(m0, a0); m1 = fmaxf(m1, a1);
            m2 = fmaxf(m2, b0v); m3 = fmaxf(m3, b1v);
        }
        // reduce over the 4 position-groups (lane bits 0..1)
        #pragma unroll
        for (int d = 1; d <= 2; d <<= 1) {
            m0 = fmaxf(m0, __shfl_xor_sync(0xffffffffu, m0, d));
            m1 = fmaxf(m1, __shfl_xor_sync(0xffffffffu, m1, d));
            m2 = fmaxf(m2, __shfl_xor_sync(0xffffffffu, m2, d));
            m3 = fmaxf(m3, __shfl_xor_sync(0xffffffffu, m3, d));
        }
        if (pg == 0) {
            int q = tt >> 4;   // quarter: 16 tiles per L/4 chunk
            int* pool = (int*)g_pool + b*128;
            atomicMax(&pool[(2*og   )*4 + q], __float_as_int(m0));
            atomicMax(&pool[(2*og+ 1)*4 + q], __float_as_int(m1));
            atomicMax(&pool[(2*og+16)*4 + q], __float_as_int(m2));
            atomicMax(&pool[(2*og+17)*4 + q], __float_as_int(m3));
        }
        return;
    }

    // ======================= RESIDUAL BLOCK PASS ===========================
    const int dil  = 1 << (i & 7);
    const float* Wd = WdAll + i*64*32*2;
    const float* bd = bdAll + i*64;
    const float* W1 = W1All + i*1024;
    const float* b1 = b1All + i*32;
    const float* h_in = (i == 0) ? g_hi : ((i & 1) ? g_ha : g_hb);
    float*       h_out = (i & 1) ? g_hb : g_ha;

    // ---- stage weights first (independent of producer layer)
    const float2* Wd2 = (const float2*)Wd;
    #pragma unroll
    for (int idx = tid; idx < 1024; idx += NTHR) {
        int j = idx >> 5, c = idx & 31;
        int o0 = 2*(j & 15) + ((j >= 16) ? 32 : 0);
        float2 wa = Wd2[o0*32 + c];
        float2 wb = Wd2[(o0+1)*32 + c];
        S.wq[c][j] = make_float4(wa.x, wb.x, wa.y, wb.y);
    }
    {
        int og_ = tid & 7, c = tid >> 3;
        S.w1q[c][og_] = make_float4(W1[(2*og_   )*32 + c], W1[(2*og_+ 1)*32 + c],
                                    W1[(2*og_+16)*32 + c], W1[(2*og_+17)*32 + c]);
    }
    if (tid < 32) { S.bdf[tid] = bd[tid]; S.bdg[tid] = bd[32 + tid]; S.b1s[tid] = b1[tid]; }

    // ---- wait for producer tiles
    if (i > 0 && tid == 0) {
        int fidx = (i-1)*NTILE + tile;
        while (atomicAdd(&g_flags[fidx], 0) == 0) __nanosleep(64);
        if (tt > 0)
            while (atomicAdd(&g_flags[fidx - 1], 0) == 0) __nanosleep(64);
        __threadfence();
    }
    __syncthreads();

    // ---- stage h tiles transposed to [c][pos]
    const float* hb = h_in + b*L_*CH_;
    #pragma unroll
    for (int idx = tid; idx < 1024; idx += NTHR) {
        int c = idx & 31, lq = (idx >> 5) << 2;
        int gi = base + lq*CH_ + c;
        float4 vc;
        vc.x = h_in[gi]; vc.y = h_in[gi+32]; vc.z = h_in[gi+64]; vc.w = h_in[gi+96];
        *(float4*)&S.hTc[c][lq] = vc;
        int lp = l0 + lq - dil;
        float4 vp;
        vp.x = (lp   >= 0) ? hb[(lp  )*CH_ + c] : 0.f;
        vp.y = (lp+1 >= 0) ? hb[(lp+1)*CH_ + c] : 0.f;
        vp.z = (lp+2 >= 0) ? hb[(lp+2)*CH_ + c] : 0.f;
        vp.w = (lp+3 >= 0) ? hb[(lp+3)*CH_ + c] : 0.f;
        *(float4*)&S.hTpg[c][lq] = vp;
    }
    __syncthreads();

    // ---- dilated conv: acc = packed channel-pair, per position
    u64 accfA[4], accfB[4], accgA[4], accgB[4];
    {
        u64 bfA = *(const u64*)&S.bdf[2*og], bfB = *(const u64*)&S.bdf[2*og+16];
        u64 bgA = *(const u64*)&S.bdg[2*og], bgB = *(const u64*)&S.bdg[2*og+16];
        #pragma unroll
        for (int k = 0; k < 4; k++) {
            accfA[k] = bfA; accfB[k] = bfB; accgA[k] = bgA; accgB[k] = bgB;
        }
    }
    #pragma unroll 4
    for (int c = 0; c < 32; c++) {
        float4 hp4 = *(const float4*)&S.hTpg[c][pb4];
        float4 hc4 = *(const float4*)&S.hTc[c][pb4];
        u64 dp[4], dc[4];
        dp[0] = pack2(hp4.x, hp4.x); dp[1] = pack2(hp4.y, hp4.y);
        dp[2] = pack2(hp4.z, hp4.z); dp[3] = pack2(hp4.w, hp4.w);
        dc[0] = pack2(hc4.x, hc4.x); dc[1] = pack2(hc4.y, hc4.y);
        dc[2] = pack2(hc4.z, hc4.z); dc[3] = pack2(hc4.w, hc4.w);
        ulonglong2 wfA = *(const ulonglong2*)&S.wq[c][og];
        #pragma unroll
        for (int k = 0; k < 4; k++) { fma2(accfA[k], wfA.x, dp[k]); fma2(accfA[k], wfA.y, dc[k]); }
        ulonglong2 wfB = *(const ulonglong2*)&S.wq[c][og + 8];
        #pragma unroll
        for (int k = 0; k < 4; k++) { fma2(accfB[k], wfB.x, dp[k]); fma2(accfB[k], wfB.y, dc[k]); }
        ulonglong2 wgA = *(const ulonglong2*)&S.wq[c][16 + og];
        #pragma unroll
        for (int k = 0; k < 4; k++) { fma2(accgA[k], wgA.x, dp[k]); fma2(accgA[k], wgA.y, dc[k]); }
        ulonglong2 wgB = *(const ulonglong2*)&S.wq[c][24 + og];
        #pragma unroll
        for (int k = 0; k < 4; k++) { fma2(accgB[k], wgB.x, dp[k]); fma2(accgB[k], wgB.y, dc[k]); }
    }

    // ---- gating; write gated rows into hTpg (warp-local column stripe reuse)
    __syncwarp();
    {
        float rA0[4], rA1[4], rB0[4], rB1[4];
        #pragma unroll
        for (int k = 0; k < 4; k++) {
            float fa0, fa1, ga0, ga1, fb0, fb1, gb0, gb1;
            unpack2(accfA[k], fa0, fa1); unpack2(accgA[k], ga0, ga1);
            unpack2(accfB[k], fb0, fb1); unpack2(accgB[k], gb0, gb1);
            rA0[k] = gate(fa0, ga0); rA1[k] = gate(fa1, ga1);
            rB0[k] = gate(fb0, gb0); rB1[k] = gate(fb1, gb1);
        }
        *(float4*)&S.hTpg[2*og   ][pb4] = make_float4(rA0[0], rA0[1], rA0[2], rA0[3]);
        *(float4*)&S.hTpg[2*og+ 1][pb4] = make_float4(rA1[0], rA1[1], rA1[2], rA1[3]);
        *(float4*)&S.hTpg[2*og+16][pb4] = make_float4(rB0[0], rB0[1], rB0[2], rB0[3]);
        *(float4*)&S.hTpg[2*og+17][pb4] = make_float4(rB1[0], rB1[1], rB1[2], rB1[3]);
    }
    __syncwarp();

    // ---- skip = W1 @ gated + b1
    u64 accsA[4], accsB[4];
    {
        u64 bsA = *(const u64*)&S.b1s[2*og], bsB = *(const u64*)&S.b1s[2*og+16];
        #pragma unroll
        for (int k = 0; k < 4; k++) { accsA[k] = bsA; accsB[k] = bsB; }
    }
    #pragma unroll 4
    for (int c = 0; c < 32; c++) {
        float4 gg = *(const float4*)&S.hTpg[c][pb4];
        u64 d0 = pack2(gg.x, gg.x), d1 = pack2(gg.y, gg.y);
        u64 d2 = pack2(gg.z, gg.z), d3 = pack2(gg.w, gg.w);
        ulonglong2 wp = *(const ulonglong2*)&S.w1q[c][og];
        fma2(accsA[0], wp.x, d0); fma2(accsB[0], wp.y, d0);
        fma2(accsA[1], wp.x, d1); fma2(accsB[1], wp.y, d1);
        fma2(accsA[2], wp.x, d2); fma2(accsB[2], wp.y, d2);
        fma2(accsA[3], wp.x, d3); fma2(accsB[3], wp.y, d3);
    }

    // ---- residual: h_out = h_in + skip; adjacent channel pairs -> STG.64
    {
        float4 h0 = *(const float4*)&S.hTc[2*og   ][pb4];
        float4 h1 = *(const float4*)&S.hTc[2*og+ 1][pb4];
        float4 h2 = *(const float4*)&S.hTc[2*og+16][pb4];
        float4 h3 = *(const float4*)&S.hTc[2*og+17][pb4];
        float h0a[4] = {h0.x,h0.y,h0.z,h0.w}, h1a[4] = {h1.x,h1.y,h1.z,h1.w};
        float h2a[4] = {h2.x,h2.y,h2.z,h2.w}, h3a[4] = {h3.x,h3.y,h3.z,h3.w};
        #pragma unroll
        for (int k = 0; k < 4; k++) {
            float sa0, sa1, sb0, sb1;
            unpack2(accsA[k], sa0, sa1);
            unpack2(accsB[k], sb0, sb1);
            int gi = base + (pb4 + k)*CH_;
            *(float2*)&h_out[gi + 2*og]      = make_float2(h0a[k] + sa0, h1a[k] + sa1);
            *(float2*)&h_out[gi + 2*og + 16] = make_float2(h2a[k] + sb0, h3a[k] + sb1);
        }
    }

    // ---- publish this tile's completion
    __syncthreads();
    if (tid == 0) {
        __threadfence();
        atomicExch(&g_flags[i*NTILE + tile], 1);
    }
}

// ---------------------------------------------------------------------------
// FC head: 128 -> 64 (relu) -> 10. PDL: fW1 staged (coalesced, padded smem)
// before the dependency sync so the DRAM fetch overlaps the chain's tail.
// ---------------------------------------------------------------------------
__global__ void fc_kernel(const float* __restrict__ fW1, const float* __restrict__ fb1,
                          const float* __restrict__ fW2, const float* __restrict__ fb2,
                          float* __restrict__ out)
{
    __shared__ float sw[64*129];   // fW1, row stride 129 -> conflict-free reads
    __shared__ float ps[128], h1[64];
    const int b = blockIdx.x, tid = threadIdx.x;

    #pragma unroll 8
    for (int i = tid; i < 8192; i += 64) {
        int r = i >> 7, c = i & 127;
        sw[r*129 + c] = fW1[i];            // coalesced LDG
    }
    float bias = fb1[tid];
    cudaGridDependencySynchronize();

    ps[tid]      = g_pool[b*128 + tid];
    ps[tid + 64] = g_pool[b*128 + 64 + tid];
    __syncthreads();

    float acc = bias;
    #pragma unroll 16
    for (int k = 0; k < 128; k++) acc = fmaf(sw[tid*129 + k], ps[k], acc);
    h1[tid] = fmaxf(acc, 0.f);
    __syncthreads();
    if (tid < 10) {
        float a2 = fb2[tid];
        #pragma unroll 8
        for (int k = 0; k < 64; k++) a2 = fmaf(fW2[tid*64 + k], h1[k], a2);
        out[b*10 + tid] = a2;
    }
}

// ---------------------------------------------------------------------------
extern "C" void kernel_launch(void* const* d_in, const int* in_sizes, int n_in,
                              void* d_out, int out_size)
{
    const float* x   = (const float*)d_in[0];
    const float* W0  = (const float*)d_in[1];
    const float* b0  = (const float*)d_in[2];
    const float* Wd  = (const float*)d_in[3];   // (24, 64, 32, 2)
    const float* bd  = (const float*)d_in[4];   // (24, 64)
    const float* W1  = (const float*)d_in[5];   // (24, 32, 32)
    const float* b1  = (const float*)d_in[6];   // (24, 32)
    const float* Wf  = (const float*)d_in[7];
    const float* bf  = (const float*)d_in[8];
    const float* fW1 = (const float*)d_in[9];
    const float* fb1 = (const float*)d_in[10];
    const float* fW2 = (const float*)d_in[11];
    const float* fb2 = (const float*)d_in[12];
    float* out = (float*)d_out;

    static bool attr_done = false;
    if (!attr_done) {
        cudaFuncSetAttribute(chain_kernel,
            cudaFuncAttributeMaxDynamicSharedMemorySize, SMEM_BYTES);
        attr_done = true;
    }

    init_kernel<<<(B_*L_*CH_ + 255)/256, 256>>>(x, W0, b0);

    // 24 layers + fused pool, one persistent flag-chained grid
    chain_kernel<<<NGRID, NTHR, SMEM_BYTES>>>(Wd, bd, W1, b1, Wf, bf);

    // FC head with PDL: weight staging overlaps the chain tail
    cudaLaunchAttribute pdl[1];
    pdl[0].id = cudaLaunchAttributeProgrammaticStreamSerialization;
    pdl[0].val.programmaticStreamSerializationAllowed = 1;
    cudaLaunchConfig_t cfgF = {};
    cfgF.gridDim  = dim3(B_);
    cfgF.blockDim = dim3(64);
    cfgF.dynamicSmemBytes = 0;
    cfgF.stream = 0;
    cfgF.attrs = pdl;
    cfgF.numAttrs = 1;
    cudaLaunchKernelEx(&cfgF, fc_kernel, fW1, fb1, fW2, fb2, out);
}

// round 13
// speedup vs baseline: 1.2775x; 1.0045x over previous
#include <cuda_runtime.h>

#define B_    16
#define L_    8192
#define CH_   32
#define NBLK  24
#define TILE  128
#define PSTR  132     // row stride ≡ 4 (mod 32), 16B aligned
#define NTHR  256
#define NTILE 1024    // tiles per layer = (L_/TILE) * B_
#define NGRID ((NBLK+1)*NTILE)   // +1 pool "layer"

typedef unsigned long long u64;

// Scratch (device globals: allocation-free per harness rules).
// g_flags/g_pool start BSS-zero; fc_kernel re-zeroes them at the end of every
// call so each graph replay begins from the same state.
__device__ float g_hi[B_*L_*CH_];    // init conv output (skip_sum = h_fin - h_init)
__device__ float g_ha[B_*L_*CH_];
__device__ float g_hb[B_*L_*CH_];
__device__ float g_pool[B_*128];     // pooled features (atomicMax-accumulated)
__device__ int   g_flags[NBLK*NTILE];// cross-layer completion flags

// ---- packed f32x2 helpers (FFMA2 is PTX-only; ptxas won't auto-fuse) ------
__device__ __forceinline__ u64 pack2(float a, float b) {
    u64 r; asm("mov.b64 %0, {%1,%2};" : "=l"(r) : "f"(a), "f"(b)); return r;
}
__device__ __forceinline__ void unpack2(u64 v, float& a, float& b) {
    asm("mov.b64 {%0,%1}, %2;" : "=f"(a), "=f"(b) : "l"(v));
}
__device__ __forceinline__ void fma2(u64& d, u64 a, u64 b) {
    asm("fma.rn.f32x2 %0, %1, %2, %0;" : "+l"(d) : "l"(a), "l"(b));
}

// gated = tanh(f)*sigmoid(g) = (A-1)B / ((A+1)(B+1)), A=e^{2f}, B=e^{g}
__device__ __forceinline__ float gate(float f, float g) {
    float A = __expf(2.f*f);
    float Bv = __expf(g);
    return __fdividef((A - 1.f)*Bv, (A + 1.f)*(Bv + 1.f));
}

// Channel-pair packed weights: FFMA2 weight operands come straight from LDS.
struct __align__(16) Smem {
    float4 wq[32][33];
    float4 w1q[32][8];
    float  bdf[32], bdg[32], b1s[32];
    float  hTc[32][PSTR];   // [c][pos]
    float  hTpg[32][PSTR];  // h[pos-dil] during conv, then reused for gated
};
#define SMEM_BYTES ((int)sizeof(Smem))

// ---------------------------------------------------------------------------
// 24 residual blocks + fused pool, one persistent flag-chained grid.
// bid = layer*NTILE + tile; layer NBLK = pool pass (waits on layer 23 flags).
// Layer 0 computes h_init from x inline (no separate init kernel).
// ---------------------------------------------------------------------------
__global__ void __launch_bounds__(NTHR, 4) chain_kernel(
    const float* __restrict__ x,
    const float* __restrict__ W0,    const float* __restrict__ b0,
    const float* __restrict__ WdAll, const float* __restrict__ bdAll,
    const float* __restrict__ W1All, const float* __restrict__ b1All,
    const float* __restrict__ Wf,    const float* __restrict__ bf)
{
    extern __shared__ char smem_raw[];
    Smem& S = *reinterpret_cast<Smem*>(smem_raw);

    const int tid  = threadIdx.x;
    const int bid  = blockIdx.x;
    const int i    = bid >> 10;          // layer (NBLK = pool pass)
    const int tile = bid & (NTILE - 1);
    const int b    = tile >> 6;
    const int tt   = tile & 63;
    const int l0   = tt * TILE;
    const int base = (b*L_ + l0) * CH_;

    const int w   = tid >> 5;
    const int og  = (tid >> 2) & 7;     // channel-pair group
    const int pg  = tid & 3;            // position group
    const int pb4 = w*16 + 4*pg;        // this thread's 4 positions

    // ======================= POOL PASS (i == NBLK) =========================
    if (i == NBLK) {
        // stage Wf packed (independent of producers)
        {
            int og_ = tid & 7, c = tid >> 3;
            S.w1q[c][og_] = make_float4(Wf[(2*og_   )*32 + c], Wf[(2*og_+ 1)*32 + c],
                                        Wf[(2*og_+16)*32 + c], Wf[(2*og_+17)*32 + c]);
        }
        if (tid < 32) S.b1s[tid] = bf[tid];

        if (tid == 0) {
            int fidx = (NBLK-1)*NTILE + tile;
            while (atomicAdd(&g_flags[fidx], 0) == 0) __nanosleep(64);
            __threadfence();
        }
        __syncthreads();

        // stage sv = relu(h_fin - h_init), transposed [c][pos]
        #pragma unroll
        for (int idx = tid; idx < 1024; idx += NTHR) {
            int c = idx & 31, lq = (idx >> 5) << 2;
            int gi = base + lq*CH_ + c;
            float4 v;
            v.x = fmaxf(g_hb[gi]    - g_hi[gi],    0.f);
            v.y = fmaxf(g_hb[gi+32] - g_hi[gi+32], 0.f);
            v.z = fmaxf(g_hb[gi+64] - g_hi[gi+64], 0.f);
            v.w = fmaxf(g_hb[gi+96] - g_hi[gi+96], 0.f);
            *(float4*)&S.hTc[c][lq] = v;
        }
        __syncthreads();

        // y = relu(Wf @ sv + bf), channel-pair FFMA2 matvec
        u64 accA[4], accB[4];
        {
            u64 bA = *(const u64*)&S.b1s[2*og], bB = *(const u64*)&S.b1s[2*og+16];
            #pragma unroll
            for (int k = 0; k < 4; k++) { accA[k] = bA; accB[k] = bB; }
        }
        #pragma unroll 4
        for (int c = 0; c < 32; c++) {
            float4 gg = *(const float4*)&S.hTc[c][pb4];
            u64 d0 = pack2(gg.x, gg.x), d1 = pack2(gg.y, gg.y);
            u64 d2 = pack2(gg.z, gg.z), d3 = pack2(gg.w, gg.w);
            ulonglong2 wp = *(const ulonglong2*)&S.w1q[c][og];
            fma2(accA[0], wp.x, d0); fma2(accB[0], wp.y, d0);
            fma2(accA[1], wp.x, d1); fma2(accB[1], wp.y, d1);
            fma2(accA[2], wp.x, d2); fma2(accB[2], wp.y, d2);
            fma2(accA[3], wp.x, d3); fma2(accB[3], wp.y, d3);
        }
        // relu folded into max (init 0); per-thread max over 4 positions
        float m0 = 0.f, m1 = 0.f, m2 = 0.f, m3 = 0.f;
        #pragma unroll
        for (int k = 0; k < 4; k++) {
            float a0, a1, b0v, b1v;
            unpack2(accA[k], a0, a1);
            unpack2(accB[k], b0v, b1v);
            m0 = fmaxf(m0, a0); m1 = fmaxf(m1, a1);
            m2 = fmaxf(m2, b0v); m3 = fmaxf(m3, b1v);
        }
        // reduce over the 4 position-groups (lane bits 0..1)
        #pragma unroll
        for (int d = 1; d <= 2; d <<= 1) {
            m0 = fmaxf(m0, __shfl_xor_sync(0xffffffffu, m0, d));
            m1 = fmaxf(m1, __shfl_xor_sync(0xffffffffu, m1, d));
            m2 = fmaxf(m2, __shfl_xor_sync(0xffffffffu, m2, d));
            m3 = fmaxf(m3, __shfl_xor_sync(0xffffffffu, m3, d));
        }
        if (pg == 0) {
            int q = tt >> 4;   // quarter: 16 tiles per L/4 chunk
            int* pool = (int*)g_pool + b*128;
            atomicMax(&pool[(2*og   )*4 + q], __float_as_int(m0));
            atomicMax(&pool[(2*og+ 1)*4 + q], __float_as_int(m1));
            atomicMax(&pool[(2*og+16)*4 + q], __float_as_int(m2));
            atomicMax(&pool[(2*og+17)*4 + q], __float_as_int(m3));
        }
        return;
    }

    // ======================= RESIDUAL BLOCK PASS ===========================
    const int dil  = 1 << (i & 7);
    const float* Wd = WdAll + i*64*32*2;
    const float* bd = bdAll + i*64;
    const float* W1 = W1All + i*1024;
    const float* b1 = b1All + i*32;
    const float* h_in = (i & 1) ? g_ha : g_hb;   // only used for i > 0
    float*       h_out = (i & 1) ? g_hb : g_ha;

    // ---- stage weights first (independent of producer layer)
    const float2* Wd2 = (const float2*)Wd;
    #pragma unroll
    for (int idx = tid; idx < 1024; idx += NTHR) {
        int j = idx >> 5, c = idx & 31;
        int o0 = 2*(j & 15) + ((j >= 16) ? 32 : 0);
        float2 wa = Wd2[o0*32 + c];
        float2 wb = Wd2[(o0+1)*32 + c];
        S.wq[c][j] = make_float4(wa.x, wb.x, wa.y, wb.y);
    }
    {
        int og_ = tid & 7, c = tid >> 3;
        S.w1q[c][og_] = make_float4(W1[(2*og_   )*32 + c], W1[(2*og_+ 1)*32 + c],
                                    W1[(2*og_+16)*32 + c], W1[(2*og_+17)*32 + c]);
    }
    if (tid < 32) { S.bdf[tid] = bd[tid]; S.bdg[tid] = bd[32 + tid]; S.b1s[tid] = b1[tid]; }

    if (i == 0) {
        // ---- layer 0: compute h_init from x inline (K=2, dil=1 causal conv)
        // h(l) = W0[c][0]*x[l-1] + W0[c][1]*x[l] + b0[c]  (same fma order as
        // the old init kernel -> bitwise identical h_init)
        const float* xb = x + b*L_;
        const int c = tid & 31;
        const float w0a = W0[2*c], w0b = W0[2*c + 1], bb0 = b0[c];
        #pragma unroll
        for (int idx = tid; idx < 1024; idx += NTHR) {
            int lq = (idx >> 5) << 2;       // c is constant per thread
            int l = l0 + lq;
            float xm2 = (l >= 2) ? xb[l-2] : 0.f;
            float xm1 = (l >= 1) ? xb[l-1] : 0.f;
            float x0 = xb[l], x1 = xb[l+1], x2 = xb[l+2], x3 = xb[l+3];
            float hm1 = (l >= 1) ? fmaf(w0a, xm2, fmaf(w0b, xm1, bb0)) : 0.f;
            float h0  = fmaf(w0a, xm1, fmaf(w0b, x0, bb0));
            float h1  = fmaf(w0a, x0,  fmaf(w0b, x1, bb0));
            float h2  = fmaf(w0a, x1,  fmaf(w0b, x2, bb0));
            float h3  = fmaf(w0a, x2,  fmaf(w0b, x3, bb0));
            *(float4*)&S.hTc[c][lq]  = make_float4(h0, h1, h2, h3);
            *(float4*)&S.hTpg[c][lq] = make_float4(hm1, h0, h1, h2);
            int gi = base + lq*CH_ + c;     // persist h_init for the pool pass
            g_hi[gi]      = h0;
            g_hi[gi + 32] = h1;
            g_hi[gi + 64] = h2;
            g_hi[gi + 96] = h3;
        }
        __syncthreads();
    } else {
        // ---- wait for producer tiles
        if (tid == 0) {
            int fidx = (i-1)*NTILE + tile;
            while (atomicAdd(&g_flags[fidx], 0) == 0) __nanosleep(64);
            if (tt > 0)
                while (atomicAdd(&g_flags[fidx - 1], 0) == 0) __nanosleep(64);
            __threadfence();
        }
        __syncthreads();

        // ---- stage h tiles transposed to [c][pos]
        const float* hb = h_in + b*L_*CH_;
        #pragma unroll
        for (int idx = tid; idx < 1024; idx += NTHR) {
            int c = idx & 31, lq = (idx >> 5) << 2;
            int gi = base + lq*CH_ + c;
            float4 vc;
            vc.x = h_in[gi]; vc.y = h_in[gi+32]; vc.z = h_in[gi+64]; vc.w = h_in[gi+96];
            *(float4*)&S.hTc[c][lq] = vc;
            int lp = l0 + lq - dil;
            float4 vp;
            vp.x = (lp   >= 0) ? hb[(lp  )*CH_ + c] : 0.f;
            vp.y = (lp+1 >= 0) ? hb[(lp+1)*CH_ + c] : 0.f;
            vp.z = (lp+2 >= 0) ? hb[(lp+2)*CH_ + c] : 0.f;
            vp.w = (lp+3 >= 0) ? hb[(lp+3)*CH_ + c] : 0.f;
            *(float4*)&S.hTpg[c][lq] = vp;
        }
        __syncthreads();
    }

    // ---- dilated conv: acc = packed channel-pair, per position
    u64 accfA[4], accfB[4], accgA[4], accgB[4];
    {
        u64 bfA = *(const u64*)&S.bdf[2*og], bfB = *(const u64*)&S.bdf[2*og+16];
        u64 bgA = *(const u64*)&S.bdg[2*og], bgB = *(const u64*)&S.bdg[2*og+16];
        #pragma unroll
        for (int k = 0; k < 4; k++) {
            accfA[k] = bfA; accfB[k] = bfB; accgA[k] = bgA; accgB[k] = bgB;
        }
    }
    #pragma unroll 4
    for (int c = 0; c < 32; c++) {
        float4 hp4 = *(const float4*)&S.hTpg[c][pb4];
        float4 hc4 = *(const float4*)&S.hTc[c][pb4];
        u64 dp[4], dc[4];
        dp[0] = pack2(hp4.x, hp4.x); dp[1] = pack2(hp4.y, hp4.y);
        dp[2] = pack2(hp4.z, hp4.z); dp[3] = pack2(hp4.w, hp4.w);
        dc[0] = pack2(hc4.x, hc4.x); dc[1] = pack2(hc4.y, hc4.y);
        dc[2] = pack2(hc4.z, hc4.z); dc[3] = pack2(hc4.w, hc4.w);
        ulonglong2 wfA = *(const ulonglong2*)&S.wq[c][og];
        #pragma unroll
        for (int k = 0; k < 4; k++) { fma2(accfA[k], wfA.x, dp[k]); fma2(accfA[k], wfA.y, dc[k]); }
        ulonglong2 wfB = *(const ulonglong2*)&S.wq[c][og + 8];
        #pragma unroll
        for (int k = 0; k < 4; k++) { fma2(accfB[k], wfB.x, dp[k]); fma2(accfB[k], wfB.y, dc[k]); }
        ulonglong2 wgA = *(const ulonglong2*)&S.wq[c][16 + og];
        #pragma unroll
        for (int k = 0; k < 4; k++) { fma2(accgA[k], wgA.x, dp[k]); fma2(accgA[k], wgA.y, dc[k]); }
        ulonglong2 wgB = *(const ulonglong2*)&S.wq[c][24 + og];
        #pragma unroll
        for (int k = 0; k < 4; k++) { fma2(accgB[k], wgB.x, dp[k]); fma2(accgB[k], wgB.y, dc[k]); }
    }

    // ---- gating; write gated rows into hTpg (warp-local column stripe reuse)
    __syncwarp();
    {
        float rA0[4], rA1[4], rB0[4], rB1[4];
        #pragma unroll
        for (int k = 0; k < 4; k++) {
            float fa0, fa1, ga0, ga1, fb0, fb1, gb0, gb1;
            unpack2(accfA[k], fa0, fa1); unpack2(accgA[k], ga0, ga1);
            unpack2(accfB[k], fb0, fb1); unpack2(accgB[k], gb0, gb1);
            rA0[k] = gate(fa0, ga0); rA1[k] = gate(fa1, ga1);
            rB0[k] = gate(fb0, gb0); rB1[k] = gate(fb1, gb1);
        }
        *(float4*)&S.hTpg[2*og   ][pb4] = make_float4(rA0[0], rA0[1], rA0[2], rA0[3]);
        *(float4*)&S.hTpg[2*og+ 1][pb4] = make_float4(rA1[0], rA1[1], rA1[2], rA1[3]);
        *(float4*)&S.hTpg[2*og+16][pb4] = make_float4(rB0[0], rB0[1], rB0[2], rB0[3]);
        *(float4*)&S.hTpg[2*og+17][pb4] = make_float4(rB1[0], rB1[1], rB1[2], rB1[3]);
    }
    __syncwarp();

    // ---- skip = W1 @ gated + b1
    u64 accsA[4], accsB[4];
    {
        u64 bsA = *(const u64*)&S.b1s[2*og], bsB = *(const u64*)&S.b1s[2*og+16];
        #pragma unroll
        for (int k = 0; k < 4; k++) { accsA[k] = bsA; accsB[k] = bsB; }
    }
    #pragma unroll 4
    for (int c = 0; c < 32; c++) {
        float4 gg = *(const float4*)&S.hTpg[c][pb4];
        u64 d0 = pack2(gg.x, gg.x), d1 = pack2(gg.y, gg.y);
        u64 d2 = pack2(gg.z, gg.z), d3 = pack2(gg.w, gg.w);
        ulonglong2 wp = *(const ulonglong2*)&S.w1q[c][og];
        fma2(accsA[0], wp.x, d0); fma2(accsB[0], wp.y, d0);
        fma2(accsA[1], wp.x, d1); fma2(accsB[1], wp.y, d1);
        fma2(accsA[2], wp.x, d2); fma2(accsB[2], wp.y, d2);
        fma2(accsA[3], wp.x, d3); fma2(accsB[3], wp.y, d3);
    }

    // ---- residual: h_out = h_in + skip; adjacent channel pairs -> STG.64
    {
        float4 h0 = *(const float4*)&S.hTc[2*og   ][pb4];
        float4 h1 = *(const float4*)&S.hTc[2*og+ 1][pb4];
        float4 h2 = *(const float4*)&S.hTc[2*og+16][pb4];
        float4 h3 = *(const float4*)&S.hTc[2*og+17][pb4];
        float h0a[4] = {h0.x,h0.y,h0.z,h0.w}, h1a[4] = {h1.x,h1.y,h1.z,h1.w};
        float h2a[4] = {h2.x,h2.y,h2.z,h2.w}, h3a[4] = {h3.x,h3.y,h3.z,h3.w};
        #pragma unroll
        for (int k = 0; k < 4; k++) {
            float sa0, sa1, sb0, sb1;
            unpack2(accsA[k], sa0, sa1);
            unpack2(accsB[k], sb0, sb1);
            int gi = base + (pb4 + k)*CH_;
            *(float2*)&h_out[gi + 2*og]      = make_float2(h0a[k] + sa0, h1a[k] + sa1);
            *(float2*)&h_out[gi + 2*og + 16] = make_float2(h2a[k] + sb0, h3a[k] + sb1);
        }
    }

    // ---- publish this tile's completion
    __syncthreads();
    if (tid == 0) {
        __threadfence();
        atomicExch(&g_flags[i*NTILE + tile], 1);
    }
}

// ---------------------------------------------------------------------------
// FC head: 128 -> 64 (relu) -> 10. PDL: fW1 staged (coalesced, padded smem)
// before the dependency sync. Afterwards, resets g_flags/g_pool so the next
// graph replay starts from a clean state.
// ---------------------------------------------------------------------------
__global__ void fc_kernel(const float* __restrict__ fW1, const float* __restrict__ fb1,
                          const float* __restrict__ fW2, const float* __restrict__ fb2,
                          float* __restrict__ out)
{
    __shared__ float sw[64*129];   // fW1, row stride 129 -> conflict-free reads
    __shared__ float ps[128], h1[64];
    const int b = blockIdx.x, tid = threadIdx.x;

    #pragma unroll 8
    for (int i = tid; i < 8192; i += 64) {
        int r = i >> 7, c = i & 127;
        sw[r*129 + c] = fW1[i];            // coalesced LDG
    }
    float bias = fb1[tid];
    cudaGridDependencySynchronize();       // all chain CTAs (incl. pool) done

    ps[tid]      = g_pool[b*128 + tid];
    ps[tid + 64] = g_pool[b*128 + 64 + tid];
    __syncthreads();

    // reset state for the next replay (safe: pool values already in smem,
    // all flag consumers finished before the dependency sync)
    g_pool[b*128 + tid]      = 0.f;
    g_pool[b*128 + 64 + tid] = 0.f;
    for (int j = b*64 + tid; j < NBLK*NTILE; j += B_*64)
        g_flags[j] = 0;

    float acc = bias;
    #pragma unroll 16
    for (int k = 0; k < 128; k++) acc = fmaf(sw[tid*129 + k], ps[k], acc);
    h1[tid] = fmaxf(acc, 0.f);
    __syncthreads();
    if (tid < 10) {
        float a2 = fb2[tid];
        #pragma unroll 8
        for (int k = 0; k < 64; k++) a2 = fmaf(fW2[tid*64 + k], h1[k], a2);
        out[b*10 + tid] = a2;
    }
}

// ---------------------------------------------------------------------------
extern "C" void kernel_launch(void* const* d_in, const int* in_sizes, int n_in,
                              void* d_out, int out_size)
{
    const float* x   = (const float*)d_in[0];
    const float* W0  = (const float*)d_in[1];
    const float* b0  = (const float*)d_in[2];
    const float* Wd  = (const float*)d_in[3];   // (24, 64, 32, 2)
    const float* bd  = (const float*)d_in[4];   // (24, 64)
    const float* W1  = (const float*)d_in[5];   // (24, 32, 32)
    const float* b1  = (const float*)d_in[6];   // (24, 32)
    const float* Wf  = (const float*)d_in[7];
    const float* bf  = (const float*)d_in[8];
    const float* fW1 = (const float*)d_in[9];
    const float* fb1 = (const float*)d_in[10];
    const float* fW2 = (const float*)d_in[11];
    const float* fb2 = (const float*)d_in[12];
    float* out = (float*)d_out;

    static bool attr_done = false;
    if (!attr_done) {
        cudaFuncSetAttribute(chain_kernel,
            cudaFuncAttributeMaxDynamicSharedMemorySize, SMEM_BYTES);
        attr_done = true;
    }

    // 24 layers (layer 0 computes h_init from x) + fused pool, one grid
    chain_kernel<<<NGRID, NTHR, SMEM_BYTES>>>(x, W0, b0, Wd, bd, W1, b1, Wf, bf);

    // FC head with PDL: weight staging overlaps the chain tail
    cudaLaunchAttribute pdl[1];
    pdl[0].id = cudaLaunchAttributeProgrammaticStreamSerialization;
    pdl[0].val.programmaticStreamSerializationAllowed = 1;
    cudaLaunchConfig_t cfgF = {};
    cfgF.gridDim  = dim3(B_);
    cfgF.blockDim = dim3(64);
    cfgF.dynamicSmemBytes = 0;
    cfgF.stream = 0;
    cfgF.attrs = pdl;
    cfgF.numAttrs = 1;
    cudaLaunchKernelEx(&cfgF, fc_kernel, fW1, fb1, fW2, fb2, out);
}

// round 14
// speedup vs baseline: 1.3607x; 1.0652x over previous
#include <cuda_runtime.h>

#define B_    16
#define L_    8192
#define CH_   32
#define NBLK  24
#define TILE  128
#define PSTR  132     // row stride ≡ 4 (mod 32), 16B aligned
#define NTHR  256
#define NTILE 1024    // tiles per layer = (L_/TILE) * B_
#define NGRID ((NBLK+1)*NTILE)   // +1 pool "layer"

typedef unsigned long long u64;

// Scratch (device globals: allocation-free per harness rules).
// h buffers are stored TRANSPOSED: [B][CH][L] (channel rows contiguous in L),
// matching the smem [c][pos] layout so staging is pure float4 streams.
// g_flags/g_pool start BSS-zero; fc_kernel re-zeroes them per call.
__device__ float g_hi[B_*CH_*L_];    // init conv output (skip_sum = h_fin - h_init)
__device__ float g_ha[B_*CH_*L_];
__device__ float g_hb[B_*CH_*L_];
__device__ float g_pool[B_*128];     // pooled features (atomicMax-accumulated)
__device__ int   g_flags[NBLK*NTILE];// cross-layer completion flags

// ---- packed f32x2 helpers (FFMA2 is PTX-only; ptxas won't auto-fuse) ------
__device__ __forceinline__ u64 pack2(float a, float b) {
    u64 r; asm("mov.b64 %0, {%1,%2};" : "=l"(r) : "f"(a), "f"(b)); return r;
}
__device__ __forceinline__ void unpack2(u64 v, float& a, float& b) {
    asm("mov.b64 {%0,%1}, %2;" : "=f"(a), "=f"(b) : "l"(v));
}
__device__ __forceinline__ void fma2(u64& d, u64 a, u64 b) {
    asm("fma.rn.f32x2 %0, %1, %2, %0;" : "+l"(d) : "l"(a), "l"(b));
}

// gated = tanh(f)*sigmoid(g) = (A-1)B / ((A+1)(B+1)), A=e^{2f}, B=e^{g}
__device__ __forceinline__ float gate(float f, float g) {
    float A = __expf(2.f*f);
    float Bv = __expf(g);
    return __fdividef((A - 1.f)*Bv, (A + 1.f)*(Bv + 1.f));
}

// Channel-pair packed weights: FFMA2 weight operands come straight from LDS.
struct __align__(16) Smem {
    float4 wq[32][33];
    float4 w1q[32][8];
    float  bdf[32], bdg[32], b1s[32];
    float  hTc[32][PSTR];   // [c][pos]
    float  hTpg[32][PSTR];  // h[pos-dil] during conv, then reused for gated
};
#define SMEM_BYTES ((int)sizeof(Smem))

// ---------------------------------------------------------------------------
// 24 residual blocks + fused pool, one persistent flag-chained grid.
// bid = layer*NTILE + tile; layer NBLK = pool pass (waits on layer 23 flags).
// Layer 0 computes h_init from x inline (no separate init kernel).
// ---------------------------------------------------------------------------
__global__ void __launch_bounds__(NTHR, 4) chain_kernel(
    const float* __restrict__ x,
    const float* __restrict__ W0,    const float* __restrict__ b0,
    const float* __restrict__ WdAll, const float* __restrict__ bdAll,
    const float* __restrict__ W1All, const float* __restrict__ b1All,
    const float* __restrict__ Wf,    const float* __restrict__ bf)
{
    extern __shared__ char smem_raw[];
    Smem& S = *reinterpret_cast<Smem*>(smem_raw);

    const int tid  = threadIdx.x;
    const int bid  = blockIdx.x;
    const int i    = bid >> 10;          // layer (NBLK = pool pass)
    const int tile = bid & (NTILE - 1);
    const int b    = tile >> 6;
    const int tt   = tile & 63;
    const int l0   = tt * TILE;

    const int w    = tid >> 5;
    const int lane = tid & 31;
    const int og   = (tid >> 2) & 7;    // channel-pair group
    const int pg   = tid & 3;           // position group
    const int pb4  = w*16 + 4*pg;       // this thread's 4 positions

    // ======================= POOL PASS (i == NBLK) =========================
    if (i == NBLK) {
        // stage Wf packed (independent of producers)
        {
            int og_ = tid & 7, c = tid >> 3;
            S.w1q[c][og_] = make_float4(Wf[(2*og_   )*32 + c], Wf[(2*og_+ 1)*32 + c],
                                        Wf[(2*og_+16)*32 + c], Wf[(2*og_+17)*32 + c]);
        }
        if (tid < 32) S.b1s[tid] = bf[tid];

        if (tid == 0) {
            int fidx = (NBLK-1)*NTILE + tile;
            while (atomicAdd(&g_flags[fidx], 0) == 0) __nanosleep(64);
            __threadfence();
        }
        __syncthreads();

        // stage sv = relu(h_fin - h_init), [c][pos]; pure float4 streams
        {
            const float* hfb = g_hb + b*CH_*L_;
            const float* hib = g_hi + b*CH_*L_;
            #pragma unroll
            for (int cc = 0; cc < 4; cc++) {
                int c = w*4 + cc;
                float4 vf = *(const float4*)&hfb[c*L_ + l0 + lane*4];
                float4 vi = *(const float4*)&hib[c*L_ + l0 + lane*4];
                float4 s = make_float4(fmaxf(vf.x - vi.x, 0.f),
                                       fmaxf(vf.y - vi.y, 0.f),
                                       fmaxf(vf.z - vi.z, 0.f),
                                       fmaxf(vf.w - vi.w, 0.f));
                *(float4*)&S.hTc[c][lane*4] = s;
            }
        }
        __syncthreads();

        // y = relu(Wf @ sv + bf), channel-pair FFMA2 matvec
        u64 accA[4], accB[4];
        {
            u64 bA = *(const u64*)&S.b1s[2*og], bB = *(const u64*)&S.b1s[2*og+16];
            #pragma unroll
            for (int k = 0; k < 4; k++) { accA[k] = bA; accB[k] = bB; }
        }
        #pragma unroll 4
        for (int c = 0; c < 32; c++) {
            float4 gg = *(const float4*)&S.hTc[c][pb4];
            u64 d0 = pack2(gg.x, gg.x), d1 = pack2(gg.y, gg.y);
            u64 d2 = pack2(gg.z, gg.z), d3 = pack2(gg.w, gg.w);
            ulonglong2 wp = *(const ulonglong2*)&S.w1q[c][og];
            fma2(accA[0], wp.x, d0); fma2(accB[0], wp.y, d0);
            fma2(accA[1], wp.x, d1); fma2(accB[1], wp.y, d1);
            fma2(accA[2], wp.x, d2); fma2(accB[2], wp.y, d2);
            fma2(accA[3], wp.x, d3); fma2(accB[3], wp.y, d3);
        }
        // relu folded into max (init 0); per-thread max over 4 positions
        float m0 = 0.f, m1 = 0.f, m2 = 0.f, m3 = 0.f;
        #pragma unroll
        for (int k = 0; k < 4; k++) {
            float a0, a1, b0v, b1v;
            unpack2(accA[k], a0, a1);
            unpack2(accB[k], b0v, b1v);
            m0 = fmaxf(m0, a0); m1 = fmaxf(m1, a1);
            m2 = fmaxf(m2, b0v); m3 = fmaxf(m3, b1v);
        }
        // reduce over the 4 position-groups (lane bits 0..1)
        #pragma unroll
        for (int d = 1; d <= 2; d <<= 1) {
            m0 = fmaxf(m0, __shfl_xor_sync(0xffffffffu, m0, d));
            m1 = fmaxf(m1, __shfl_xor_sync(0xffffffffu, m1, d));
            m2 = fmaxf(m2, __shfl_xor_sync(0xffffffffu, m2, d));
            m3 = fmaxf(m3, __shfl_xor_sync(0xffffffffu, m3, d));
        }
        if (pg == 0) {
            int q = tt >> 4;   // quarter: 16 tiles per L/4 chunk
            int* pool = (int*)g_pool + b*128;
            atomicMax(&pool[(2*og   )*4 + q], __float_as_int(m0));
            atomicMax(&pool[(2*og+ 1)*4 + q], __float_as_int(m1));
            atomicMax(&pool[(2*og+16)*4 + q], __float_as_int(m2));
            atomicMax(&pool[(2*og+17)*4 + q], __float_as_int(m3));
        }
        return;
    }

    // ======================= RESIDUAL BLOCK PASS ===========================
    const int dil  = 1 << (i & 7);
    const float* Wd = WdAll + i*64*32*2;
    const float* bd = bdAll + i*64;
    const float* W1 = W1All + i*1024;
    const float* b1 = b1All + i*32;
    const float* h_in = (i & 1) ? g_ha : g_hb;   // only used for i > 0
    float*       h_out = (i & 1) ? g_hb : g_ha;

    // ---- stage weights first (independent of producer layer)
    const float2* Wd2 = (const float2*)Wd;
    #pragma unroll
    for (int idx = tid; idx < 1024; idx += NTHR) {
        int j = idx >> 5, c = idx & 31;
        int o0 = 2*(j & 15) + ((j >= 16) ? 32 : 0);
        float2 wa = Wd2[o0*32 + c];
        float2 wb = Wd2[(o0+1)*32 + c];
        S.wq[c][j] = make_float4(wa.x, wb.x, wa.y, wb.y);
    }
    {
        int og_ = tid & 7, c = tid >> 3;
        S.w1q[c][og_] = make_float4(W1[(2*og_   )*32 + c], W1[(2*og_+ 1)*32 + c],
                                    W1[(2*og_+16)*32 + c], W1[(2*og_+17)*32 + c]);
    }
    if (tid < 32) { S.bdf[tid] = bd[tid]; S.bdg[tid] = bd[32 + tid]; S.b1s[tid] = b1[tid]; }

    if (i == 0) {
        // ---- layer 0: compute h_init from x inline (K=2, dil=1 causal conv)
        // same fma order as before -> bitwise identical h_init
        const float* xb = x + b*L_;
        const int c0 = tid & 31;
        const float w0a = W0[2*c0], w0b = W0[2*c0 + 1], bb0 = b0[c0];
        #pragma unroll
        for (int n = 0; n < 4; n++) {
            int lq = ((tid >> 5) + 8*n) * 4;
            int l = l0 + lq;
            float xm2 = (l >= 2) ? xb[l-2] : 0.f;
            float xm1 = (l >= 1) ? xb[l-1] : 0.f;
            float x0 = xb[l], x1 = xb[l+1], x2 = xb[l+2], x3 = xb[l+3];
            float hm1 = (l >= 1) ? fmaf(w0a, xm2, fmaf(w0b, xm1, bb0)) : 0.f;
            float h0  = fmaf(w0a, xm1, fmaf(w0b, x0, bb0));
            float h1  = fmaf(w0a, x0,  fmaf(w0b, x1, bb0));
            float h2  = fmaf(w0a, x1,  fmaf(w0b, x2, bb0));
            float h3  = fmaf(w0a, x2,  fmaf(w0b, x3, bb0));
            *(float4*)&S.hTc[c0][lq]  = make_float4(h0, h1, h2, h3);
            *(float4*)&S.hTpg[c0][lq] = make_float4(hm1, h0, h1, h2);
        }
        __syncthreads();
        // persist h_init transposed (coalesced float4 rows via smem)
        #pragma unroll
        for (int cc = 0; cc < 4; cc++) {
            int c = w*4 + cc;
            float4 v = *(const float4*)&S.hTc[c][lane*4];
            *(float4*)&g_hi[(b*CH_ + c)*L_ + l0 + lane*4] = v;
        }
    } else {
        // ---- wait for producer tiles
        if (tid == 0) {
            int fidx = (i-1)*NTILE + tile;
            while (atomicAdd(&g_flags[fidx], 0) == 0) __nanosleep(64);
            if (tt > 0)
                while (atomicAdd(&g_flags[fidx - 1], 0) == 0) __nanosleep(64);
            __threadfence();
        }
        __syncthreads();

        // ---- stage h tiles: transposed global -> pure float4 streams
        const float* hinb = h_in + b*CH_*L_;
        const bool fastp = (dil >= 4) && (l0 >= dil);
        #pragma unroll
        for (int cc = 0; cc < 4; cc++) {
            const int c = w*4 + cc;
            const float* rowc = hinb + c*L_;
            float4 vc = *(const float4*)&rowc[l0 + lane*4];
            *(float4*)&S.hTc[c][lane*4] = vc;
            if (fastp) {
                float4 vp = *(const float4*)&rowc[l0 - dil + lane*4];
                *(float4*)&S.hTpg[c][lane*4] = vp;
            } else {
                int lb = l0 + lane*4 - dil;
                float4 vp;
                vp.x = (lb   >= 0) ? rowc[lb  ] : 0.f;
                vp.y = (lb+1 >= 0) ? rowc[lb+1] : 0.f;
                vp.z = (lb+2 >= 0) ? rowc[lb+2] : 0.f;
                vp.w = (lb+3 >= 0) ? rowc[lb+3] : 0.f;
                *(float4*)&S.hTpg[c][lane*4] = vp;
            }
        }
        __syncthreads();
    }

    // ---- dilated conv: acc = packed channel-pair, per position
    u64 accfA[4], accfB[4], accgA[4], accgB[4];
    {
        u64 bfA = *(const u64*)&S.bdf[2*og], bfB = *(const u64*)&S.bdf[2*og+16];
        u64 bgA = *(const u64*)&S.bdg[2*og], bgB = *(const u64*)&S.bdg[2*og+16];
        #pragma unroll
        for (int k = 0; k < 4; k++) {
            accfA[k] = bfA; accfB[k] = bfB; accgA[k] = bgA; accgB[k] = bgB;
        }
    }
    #pragma unroll 4
    for (int c = 0; c < 32; c++) {
        float4 hp4 = *(const float4*)&S.hTpg[c][pb4];
        float4 hc4 = *(const float4*)&S.hTc[c][pb4];
        u64 dp[4], dc[4];
        dp[0] = pack2(hp4.x, hp4.x); dp[1] = pack2(hp4.y, hp4.y);
        dp[2] = pack2(hp4.z, hp4.z); dp[3] = pack2(hp4.w, hp4.w);
        dc[0] = pack2(hc4.x, hc4.x); dc[1] = pack2(hc4.y, hc4.y);
        dc[2] = pack2(hc4.z, hc4.z); dc[3] = pack2(hc4.w, hc4.w);
        ulonglong2 wfA = *(const ulonglong2*)&S.wq[c][og];
        #pragma unroll
        for (int k = 0; k < 4; k++) { fma2(accfA[k], wfA.x, dp[k]); fma2(accfA[k], wfA.y, dc[k]); }
        ulonglong2 wfB = *(const ulonglong2*)&S.wq[c][og + 8];
        #pragma unroll
        for (int k = 0; k < 4; k++) { fma2(accfB[k], wfB.x, dp[k]); fma2(accfB[k], wfB.y, dc[k]); }
        ulonglong2 wgA = *(const ulonglong2*)&S.wq[c][16 + og];
        #pragma unroll
        for (int k = 0; k < 4; k++) { fma2(accgA[k], wgA.x, dp[k]); fma2(accgA[k], wgA.y, dc[k]); }
        ulonglong2 wgB = *(const ulonglong2*)&S.wq[c][24 + og];
        #pragma unroll
        for (int k = 0; k < 4; k++) { fma2(accgB[k], wgB.x, dp[k]); fma2(accgB[k], wgB.y, dc[k]); }
    }

    // ---- gating; write gated rows into hTpg (warp-local column stripe reuse)
    __syncwarp();
    {
        float rA0[4], rA1[4], rB0[4], rB1[4];
        #pragma unroll
        for (int k = 0; k < 4; k++) {
            float fa0, fa1, ga0, ga1, fb0, fb1, gb0, gb1;
            unpack2(accfA[k], fa0, fa1); unpack2(accgA[k], ga0, ga1);
            unpack2(accfB[k], fb0, fb1); unpack2(accgB[k], gb0, gb1);
            rA0[k] = gate(fa0, ga0); rA1[k] = gate(fa1, ga1);
            rB0[k] = gate(fb0, gb0); rB1[k] = gate(fb1, gb1);
        }
        *(float4*)&S.hTpg[2*og   ][pb4] = make_float4(rA0[0], rA0[1], rA0[2], rA0[3]);
        *(float4*)&S.hTpg[2*og+ 1][pb4] = make_float4(rA1[0], rA1[1], rA1[2], rA1[3]);
        *(float4*)&S.hTpg[2*og+16][pb4] = make_float4(rB0[0], rB0[1], rB0[2], rB0[3]);
        *(float4*)&S.hTpg[2*og+17][pb4] = make_float4(rB1[0], rB1[1], rB1[2], rB1[3]);
    }
    __syncwarp();

    // ---- skip = W1 @ gated + b1
    u64 accsA[4], accsB[4];
    {
        u64 bsA = *(const u64*)&S.b1s[2*og], bsB = *(const u64*)&S.b1s[2*og+16];
        #pragma unroll
        for (int k = 0; k < 4; k++) { accsA[k] = bsA; accsB[k] = bsB; }
    }
    #pragma unroll 4
    for (int c = 0; c < 32; c++) {
        float4 gg = *(const float4*)&S.hTpg[c][pb4];
        u64 d0 = pack2(gg.x, gg.x), d1 = pack2(gg.y, gg.y);
        u64 d2 = pack2(gg.z, gg.z), d3 = pack2(gg.w, gg.w);
        ulonglong2 wp = *(const ulonglong2*)&S.w1q[c][og];
        fma2(accsA[0], wp.x, d0); fma2(accsB[0], wp.y, d0);
        fma2(accsA[1], wp.x, d1); fma2(accsB[1], wp.y, d1);
        fma2(accsA[2], wp.x, d2); fma2(accsB[2], wp.y, d2);
        fma2(accsA[3], wp.x, d3); fma2(accsB[3], wp.y, d3);
    }

    // ---- residual: h_out = h_in + skip; transposed rows -> 4x STG.128
    {
        float4 h0 = *(const float4*)&S.hTc[2*og   ][pb4];
        float4 h1 = *(const float4*)&S.hTc[2*og+ 1][pb4];
        float4 h2 = *(const float4*)&S.hTc[2*og+16][pb4];
        float4 h3 = *(const float4*)&S.hTc[2*og+17][pb4];
        float sa0[4], sa1[4], sb0[4], sb1[4];
        #pragma unroll
        for (int k = 0; k < 4; k++) {
            unpack2(accsA[k], sa0[k], sa1[k]);
            unpack2(accsB[k], sb0[k], sb1[k]);
        }
        float* houtb = h_out + b*CH_*L_;
        *(float4*)&houtb[(2*og   )*L_ + l0 + pb4] =
            make_float4(h0.x + sa0[0], h0.y + sa0[1], h0.z + sa0[2], h0.w + sa0[3]);
        *(float4*)&houtb[(2*og+ 1)*L_ + l0 + pb4] =
            make_float4(h1.x + sa1[0], h1.y + sa1[1], h1.z + sa1[2], h1.w + sa1[3]);
        *(float4*)&houtb[(2*og+16)*L_ + l0 + pb4] =
            make_float4(h2.x + sb0[0], h2.y + sb0[1], h2.z + sb0[2], h2.w + sb0[3]);
        *(float4*)&houtb[(2*og+17)*L_ + l0 + pb4] =
            make_float4(h3.x + sb1[0], h3.y + sb1[1], h3.z + sb1[2], h3.w + sb1[3]);
    }

    // ---- publish this tile's completion
    __syncthreads();
    if (tid == 0) {
        __threadfence();
        atomicExch(&g_flags[i*NTILE + tile], 1);
    }
}

// ---------------------------------------------------------------------------
// FC head: 128 -> 64 (relu) -> 10. PDL: fW1 staged (coalesced, padded smem)
// before the dependency sync. Afterwards, resets g_flags/g_pool so the next
// graph replay starts from a clean state.
// ---------------------------------------------------------------------------
__global__ void fc_kernel(const float* __restrict__ fW1, const float* __restrict__ fb1,
                          const float* __restrict__ fW2, const float* __restrict__ fb2,
                          float* __restrict__ out)
{
    __shared__ float sw[64*129];   // fW1, row stride 129 -> conflict-free reads
    __shared__ float ps[128], h1[64];
    const int b = blockIdx.x, tid = threadIdx.x;

    #pragma unroll 8
    for (int i = tid; i < 8192; i += 64) {
        int r = i >> 7, c = i & 127;
        sw[r*129 + c] = fW1[i];            // coalesced LDG
    }
    float bias = fb1[tid];
    cudaGridDependencySynchronize();       // all chain CTAs (incl. pool) done

    ps[tid]      = g_pool[b*128 + tid];
    ps[tid + 64] = g_pool[b*128 + 64 + tid];
    __syncthreads();

    // reset state for the next replay (safe: pool values already in smem,
    // all flag consumers finished before the dependency sync)
    g_pool[b*128 + tid]      = 0.f;
    g_pool[b*128 + 64 + tid] = 0.f;
    for (int j = b*64 + tid; j < NBLK*NTILE; j += B_*64)
        g_flags[j] = 0;

    float acc = bias;
    #pragma unroll 16
    for (int k = 0; k < 128; k++) acc = fmaf(sw[tid*129 + k], ps[k], acc);
    h1[tid] = fmaxf(acc, 0.f);
    __syncthreads();
    if (tid < 10) {
        float a2 = fb2[tid];
        #pragma unroll 8
        for (int k = 0; k < 64; k++) a2 = fmaf(fW2[tid*64 + k], h1[k], a2);
        out[b*10 + tid] = a2;
    }
}

// ---------------------------------------------------------------------------
extern "C" void kernel_launch(void* const* d_in, const int* in_sizes, int n_in,
                              void* d_out, int out_size)
{
    const float* x   = (const float*)d_in[0];
    const float* W0  = (const float*)d_in[1];
    const float* b0  = (const float*)d_in[2];
    const float* Wd  = (const float*)d_in[3];   // (24, 64, 32, 2)
    const float* bd  = (const float*)d_in[4];   // (24, 64)
    const float* W1  = (const float*)d_in[5];   // (24, 32, 32)
    const float* b1  = (const float*)d_in[6];   // (24, 32)
    const float* Wf  = (const float*)d_in[7];
    const float* bf  = (const float*)d_in[8];
    const float* fW1 = (const float*)d_in[9];
    const float* fb1 = (const float*)d_in[10];
    const float* fW2 = (const float*)d_in[11];
    const float* fb2 = (const float*)d_in[12];
    float* out = (float*)d_out;

    static bool attr_done = false;
    if (!attr_done) {
        cudaFuncSetAttribute(chain_kernel,
            cudaFuncAttributeMaxDynamicSharedMemorySize, SMEM_BYTES);
        attr_done = true;
    }

    // 24 layers (layer 0 computes h_init from x) + fused pool, one grid
    chain_kernel<<<NGRID, NTHR, SMEM_BYTES>>>(x, W0, b0, Wd, bd, W1, b1, Wf, bf);

    // FC head with PDL: weight staging overlaps the chain tail
    cudaLaunchAttribute pdl[1];
    pdl[0].id = cudaLaunchAttributeProgrammaticStreamSerialization;
    pdl[0].val.programmaticStreamSerializationAllowed = 1;
    cudaLaunchConfig_t cfgF = {};
    cfgF.gridDim  = dim3(B_);
    cfgF.blockDim = dim3(64);
    cfgF.dynamicSmemBytes = 0;
    cfgF.stream = 0;
    cfgF.attrs = pdl;
    cfgF.numAttrs = 1;
    cudaLaunchKernelEx(&cfgF, fc_kernel, fW1, fb1, fW2, fb2, out);
}

// round 15
// speedup vs baseline: 1.4544x; 1.0688x over previous
#include <cuda_runtime.h>

#define B_    16
#define L_    8192
#define CH_   32
#define NBLK  24
#define TILE  128
#define PSTR  132     // row stride ≡ 4 (mod 32), 16B aligned
#define NTHR  256
#define NTILE 1024    // tiles per layer = (L_/TILE) * B_
#define NGRID ((NBLK+1)*NTILE)   // +1 pool "layer"

typedef unsigned long long u64;

// Scratch (device globals: allocation-free per harness rules).
// h buffers stored TRANSPOSED: [B][CH][L]. g_flags/g_pool start BSS-zero;
// fc_kernel re-zeroes them per call for graph-replay determinism.
__device__ float g_hi[B_*CH_*L_];
__device__ float g_ha[B_*CH_*L_];
__device__ float g_hb[B_*CH_*L_];
__device__ float g_pool[B_*128];
__device__ int   g_flags[NBLK*NTILE];

// ---- packed f32x2 helpers (FFMA2 is PTX-only; ptxas won't auto-fuse) ------
__device__ __forceinline__ u64 pack2(float a, float b) {
    u64 r; asm("mov.b64 %0, {%1,%2};" : "=l"(r) : "f"(a), "f"(b)); return r;
}
__device__ __forceinline__ void unpack2(u64 v, float& a, float& b) {
    asm("mov.b64 {%0,%1}, %2;" : "=f"(a), "=f"(b) : "l"(v));
}
__device__ __forceinline__ void fma2(u64& d, u64 a, u64 b) {
    asm("fma.rn.f32x2 %0, %1, %2, %0;" : "+l"(d) : "l"(a), "l"(b));
}

// gated = tanh(f)*sigmoid(g) = tanh(f) * (0.5*tanh(g/2) + 0.5)
// 2x MUFU.TANH instead of 2x EX2 + RCP.
__device__ __forceinline__ float gate(float f, float g) {
    float t, s;
    asm("tanh.approx.f32 %0, %1;" : "=f"(t) : "f"(f));
    float gh = g * 0.5f;
    asm("tanh.approx.f32 %0, %1;" : "=f"(s) : "f"(gh));
    return t * fmaf(s, 0.5f, 0.5f);
}

// ---- acquire/release flag ops (cheaper than ATOMG spin + MEMBAR) ----------
__device__ __forceinline__ int ld_acq(const int* p) {
    int v; asm volatile("ld.acquire.gpu.global.b32 %0, [%1];" : "=r"(v) : "l"(p) : "memory");
    return v;
}
__device__ __forceinline__ void st_rel(int* p, int v) {
    asm volatile("st.release.gpu.global.b32 [%0], %1;" :: "l"(p), "r"(v) : "memory");
}

// Channel-pair packed weights: FFMA2 weight operands come straight from LDS.
struct __align__(16) Smem {
    float4 wq[32][33];
    float4 w1q[32][8];
    float  bdf[32], bdg[32], b1s[32];
    float  hTc[32][PSTR];   // [c][pos]
    float  hTpg[32][PSTR];  // h[pos-dil] during conv, then reused for gated
};
#define SMEM_BYTES ((int)sizeof(Smem))

// ---------------------------------------------------------------------------
// 24 residual blocks + fused pool, one persistent flag-chained grid.
// ---------------------------------------------------------------------------
__global__ void __launch_bounds__(NTHR, 4) chain_kernel(
    const float* __restrict__ x,
    const float* __restrict__ W0,    const float* __restrict__ b0,
    const float* __restrict__ WdAll, const float* __restrict__ bdAll,
    const float* __restrict__ W1All, const float* __restrict__ b1All,
    const float* __restrict__ Wf,    const float* __restrict__ bf)
{
    extern __shared__ char smem_raw[];
    Smem& S = *reinterpret_cast<Smem*>(smem_raw);

    const int tid  = threadIdx.x;
    const int bid  = blockIdx.x;
    const int i    = bid >> 10;          // layer (NBLK = pool pass)
    const int tile = bid & (NTILE - 1);
    const int b    = tile >> 6;
    const int tt   = tile & 63;
    const int l0   = tt * TILE;

    const int w    = tid >> 5;
    const int lane = tid & 31;
    const int og   = (tid >> 2) & 7;    // channel-pair group
    const int pg   = tid & 3;           // position group
    const int pb4  = w*16 + 4*pg;       // this thread's 4 positions

    // ======================= POOL PASS (i == NBLK) =========================
    if (i == NBLK) {
        {
            int og_ = tid & 7, c = tid >> 3;
            S.w1q[c][og_] = make_float4(Wf[(2*og_   )*32 + c], Wf[(2*og_+ 1)*32 + c],
                                        Wf[(2*og_+16)*32 + c], Wf[(2*og_+17)*32 + c]);
        }
        if (tid < 32) S.b1s[tid] = bf[tid];

        if (tid == 0) {
            int* f = &g_flags[(NBLK-1)*NTILE + tile];
            while (ld_acq(f) == 0) __nanosleep(64);
        }
        __syncthreads();

        // stage sv = relu(h_fin - h_init), [c][pos]; pure float4 streams
        {
            const float* hfb = g_hb + b*CH_*L_;
            const float* hib = g_hi + b*CH_*L_;
            #pragma unroll
            for (int cc = 0; cc < 4; cc++) {
                int c = w*4 + cc;
                float4 vf = *(const float4*)&hfb[c*L_ + l0 + lane*4];
                float4 vi = *(const float4*)&hib[c*L_ + l0 + lane*4];
                float4 s = make_float4(fmaxf(vf.x - vi.x, 0.f),
                                       fmaxf(vf.y - vi.y, 0.f),
                                       fmaxf(vf.z - vi.z, 0.f),
                                       fmaxf(vf.w - vi.w, 0.f));
                *(float4*)&S.hTc[c][lane*4] = s;
            }
        }
        __syncthreads();

        // y = relu(Wf @ sv + bf), channel-pair FFMA2 matvec
        u64 accA[4], accB[4];
        {
            u64 bA = *(const u64*)&S.b1s[2*og], bB = *(const u64*)&S.b1s[2*og+16];
            #pragma unroll
            for (int k = 0; k < 4; k++) { accA[k] = bA; accB[k] = bB; }
        }
        #pragma unroll 8
        for (int c = 0; c < 32; c++) {
            float4 gg = *(const float4*)&S.hTc[c][pb4];
            u64 d0 = pack2(gg.x, gg.x), d1 = pack2(gg.y, gg.y);
            u64 d2 = pack2(gg.z, gg.z), d3 = pack2(gg.w, gg.w);
            ulonglong2 wp = *(const ulonglong2*)&S.w1q[c][og];
            fma2(accA[0], wp.x, d0); fma2(accB[0], wp.y, d0);
            fma2(accA[1], wp.x, d1); fma2(accB[1], wp.y, d1);
            fma2(accA[2], wp.x, d2); fma2(accB[2], wp.y, d2);
            fma2(accA[3], wp.x, d3); fma2(accB[3], wp.y, d3);
        }
        float m0 = 0.f, m1 = 0.f, m2 = 0.f, m3 = 0.f;
        #pragma unroll
        for (int k = 0; k < 4; k++) {
            float a0, a1, b0v, b1v;
            unpack2(accA[k], a0, a1);
            unpack2(accB[k], b0v, b1v);
            m0 = fmaxf(m0, a0); m1 = fmaxf(m1, a1);
            m2 = fmaxf(m2, b0v); m3 = fmaxf(m3, b1v);
        }
        #pragma unroll
        for (int d = 1; d <= 2; d <<= 1) {
            m0 = fmaxf(m0, __shfl_xor_sync(0xffffffffu, m0, d));
            m1 = fmaxf(m1, __shfl_xor_sync(0xffffffffu, m1, d));
            m2 = fmaxf(m2, __shfl_xor_sync(0xffffffffu, m2, d));
            m3 = fmaxf(m3, __shfl_xor_sync(0xffffffffu, m3, d));
        }
        if (pg == 0) {
            int q = tt >> 4;
            int* pool = (int*)g_pool + b*128;
            atomicMax(&pool[(2*og   )*4 + q], __float_as_int(m0));
            atomicMax(&pool[(2*og+ 1)*4 + q], __float_as_int(m1));
            atomicMax(&pool[(2*og+16)*4 + q], __float_as_int(m2));
            atomicMax(&pool[(2*og+17)*4 + q], __float_as_int(m3));
        }
        return;
    }

    // ======================= RESIDUAL BLOCK PASS ===========================
    const int dil  = 1 << (i & 7);
    const float* Wd = WdAll + i*64*32*2;
    const float* bd = bdAll + i*64;
    const float* W1 = W1All + i*1024;
    const float* b1 = b1All + i*32;
    const float* h_in = (i & 1) ? g_ha : g_hb;   // only used for i > 0
    float*       h_out = (i & 1) ? g_hb : g_ha;

    // ---- stage weights first (independent of producer layer)
    const float2* Wd2 = (const float2*)Wd;
    #pragma unroll
    for (int idx = tid; idx < 1024; idx += NTHR) {
        int j = idx >> 5, c = idx & 31;
        int o0 = 2*(j & 15) + ((j >= 16) ? 32 : 0);
        float2 wa = Wd2[o0*32 + c];
        float2 wb = Wd2[(o0+1)*32 + c];
        S.wq[c][j] = make_float4(wa.x, wb.x, wa.y, wb.y);
    }
    {
        int og_ = tid & 7, c = tid >> 3;
        S.w1q[c][og_] = make_float4(W1[(2*og_   )*32 + c], W1[(2*og_+ 1)*32 + c],
                                    W1[(2*og_+16)*32 + c], W1[(2*og_+17)*32 + c]);
    }
    if (tid < 32) { S.bdf[tid] = bd[tid]; S.bdg[tid] = bd[32 + tid]; S.b1s[tid] = b1[tid]; }

    if (i == 0) {
        // ---- layer 0: compute h_init from x inline (bitwise-identical order)
        const float* xb = x + b*L_;
        const int c0 = tid & 31;
        const float w0a = W0[2*c0], w0b = W0[2*c0 + 1], bb0 = b0[c0];
        #pragma unroll
        for (int n = 0; n < 4; n++) {
            int lq = ((tid >> 5) + 8*n) * 4;
            int l = l0 + lq;
            float xm2 = (l >= 2) ? xb[l-2] : 0.f;
            float xm1 = (l >= 1) ? xb[l-1] : 0.f;
            float x0 = xb[l], x1 = xb[l+1], x2 = xb[l+2], x3 = xb[l+3];
            float hm1 = (l >= 1) ? fmaf(w0a, xm2, fmaf(w0b, xm1, bb0)) : 0.f;
            float h0  = fmaf(w0a, xm1, fmaf(w0b, x0, bb0));
            float h1  = fmaf(w0a, x0,  fmaf(w0b, x1, bb0));
            float h2  = fmaf(w0a, x1,  fmaf(w0b, x2, bb0));
            float h3  = fmaf(w0a, x2,  fmaf(w0b, x3, bb0));
            *(float4*)&S.hTc[c0][lq]  = make_float4(h0, h1, h2, h3);
            *(float4*)&S.hTpg[c0][lq] = make_float4(hm1, h0, h1, h2);
        }
        __syncthreads();
        #pragma unroll
        for (int cc = 0; cc < 4; cc++) {
            int c = w*4 + cc;
            float4 v = *(const float4*)&S.hTc[c][lane*4];
            *(float4*)&g_hi[(b*CH_ + c)*L_ + l0 + lane*4] = v;
        }
    } else {
        // ---- wait for producer tiles (acquire-load spin)
        if (tid == 0) {
            int* f = &g_flags[(i-1)*NTILE + tile];
            while (ld_acq(f) == 0) __nanosleep(64);
            if (tt > 0)
                while (ld_acq(f - 1) == 0) __nanosleep(64);
        }
        __syncthreads();

        // ---- stage h tiles: transposed global -> pure float4 streams
        const float* hinb = h_in + b*CH_*L_;
        const bool fastp = (dil >= 4) && (l0 >= dil);
        #pragma unroll
        for (int cc = 0; cc < 4; cc++) {
            const int c = w*4 + cc;
            const float* rowc = hinb + c*L_;
            float4 vc = *(const float4*)&rowc[l0 + lane*4];
            *(float4*)&S.hTc[c][lane*4] = vc;
            if (fastp) {
                float4 vp = *(const float4*)&rowc[l0 - dil + lane*4];
                *(float4*)&S.hTpg[c][lane*4] = vp;
            } else {
                int lb = l0 + lane*4 - dil;
                float4 vp;
                vp.x = (lb   >= 0) ? rowc[lb  ] : 0.f;
                vp.y = (lb+1 >= 0) ? rowc[lb+1] : 0.f;
                vp.z = (lb+2 >= 0) ? rowc[lb+2] : 0.f;
                vp.w = (lb+3 >= 0) ? rowc[lb+3] : 0.f;
                *(float4*)&S.hTpg[c][lane*4] = vp;
            }
        }
        __syncthreads();
    }

    // ---- dilated conv: acc = packed channel-pair, per position
    u64 accfA[4], accfB[4], accgA[4], accgB[4];
    {
        u64 bfA = *(const u64*)&S.bdf[2*og], bfB = *(const u64*)&S.bdf[2*og+16];
        u64 bgA = *(const u64*)&S.bdg[2*og], bgB = *(const u64*)&S.bdg[2*og+16];
        #pragma unroll
        for (int k = 0; k < 4; k++) {
            accfA[k] = bfA; accfB[k] = bfB; accgA[k] = bgA; accgB[k] = bgB;
        }
    }
    #pragma unroll 8
    for (int c = 0; c < 32; c++) {
        float4 hp4 = *(const float4*)&S.hTpg[c][pb4];
        float4 hc4 = *(const float4*)&S.hTc[c][pb4];
        u64 dp[4], dc[4];
        dp[0] = pack2(hp4.x, hp4.x); dp[1] = pack2(hp4.y, hp4.y);
        dp[2] = pack2(hp4.z, hp4.z); dp[3] = pack2(hp4.w, hp4.w);
        dc[0] = pack2(hc4.x, hc4.x); dc[1] = pack2(hc4.y, hc4.y);
        dc[2] = pack2(hc4.z, hc4.z); dc[3] = pack2(hc4.w, hc4.w);
        ulonglong2 wfA = *(const ulonglong2*)&S.wq[c][og];
        #pragma unroll
        for (int k = 0; k < 4; k++) { fma2(accfA[k], wfA.x, dp[k]); fma2(accfA[k], wfA.y, dc[k]); }
        ulonglong2 wfB = *(const ulonglong2*)&S.wq[c][og + 8];
        #pragma unroll
        for (int k = 0; k < 4; k++) { fma2(accfB[k], wfB.x, dp[k]); fma2(accfB[k], wfB.y, dc[k]); }
        ulonglong2 wgA = *(const ulonglong2*)&S.wq[c][16 + og];
        #pragma unroll
        for (int k = 0; k < 4; k++) { fma2(accgA[k], wgA.x, dp[k]); fma2(accgA[k], wgA.y, dc[k]); }
        ulonglong2 wgB = *(const ulonglong2*)&S.wq[c][24 + og];
        #pragma unroll
        for (int k = 0; k < 4; k++) { fma2(accgB[k], wgB.x, dp[k]); fma2(accgB[k], wgB.y, dc[k]); }
    }

    // ---- gating; write gated rows into hTpg (warp-local column stripe reuse)
    __syncwarp();
    {
        float rA0[4], rA1[4], rB0[4], rB1[4];
        #pragma unroll
        for (int k = 0; k < 4; k++) {
            float fa0, fa1, ga0, ga1, fb0, fb1, gb0, gb1;
            unpack2(accfA[k], fa0, fa1); unpack2(accgA[k], ga0, ga1);
            unpack2(accfB[k], fb0, fb1); unpack2(accgB[k], gb0, gb1);
            rA0[k] = gate(fa0, ga0); rA1[k] = gate(fa1, ga1);
            rB0[k] = gate(fb0, gb0); rB1[k] = gate(fb1, gb1);
        }
        *(float4*)&S.hTpg[2*og   ][pb4] = make_float4(rA0[0], rA0[1], rA0[2], rA0[3]);
        *(float4*)&S.hTpg[2*og+ 1][pb4] = make_float4(rA1[0], rA1[1], rA1[2], rA1[3]);
        *(float4*)&S.hTpg[2*og+16][pb4] = make_float4(rB0[0], rB0[1], rB0[2], rB0[3]);
        *(float4*)&S.hTpg[2*og+17][pb4] = make_float4(rB1[0], rB1[1], rB1[2], rB1[3]);
    }
    __syncwarp();

    // ---- skip = W1 @ gated + b1
    u64 accsA[4], accsB[4];
    {
        u64 bsA = *(const u64*)&S.b1s[2*og], bsB = *(const u64*)&S.b1s[2*og+16];
        #pragma unroll
        for (int k = 0; k < 4; k++) { accsA[k] = bsA; accsB[k] = bsB; }
    }
    #pragma unroll 8
    for (int c = 0; c < 32; c++) {
        float4 gg = *(const float4*)&S.hTpg[c][pb4];
        u64 d0 = pack2(gg.x, gg.x), d1 = pack2(gg.y, gg.y);
        u64 d2 = pack2(gg.z, gg.z), d3 = pack2(gg.w, gg.w);
        ulonglong2 wp = *(const ulonglong2*)&S.w1q[c][og];
        fma2(accsA[0], wp.x, d0); fma2(accsB[0], wp.y, d0);
        fma2(accsA[1], wp.x, d1); fma2(accsB[1], wp.y, d1);
        fma2(accsA[2], wp.x, d2); fma2(accsB[2], wp.y, d2);
        fma2(accsA[3], wp.x, d3); fma2(accsB[3], wp.y, d3);
    }

    // ---- residual: h_out = h_in + skip; transposed rows -> 4x STG.128
    {
        float4 h0 = *(const float4*)&S.hTc[2*og   ][pb4];
        float4 h1 = *(const float4*)&S.hTc[2*og+ 1][pb4];
        float4 h2 = *(const float4*)&S.hTc[2*og+16][pb4];
        float4 h3 = *(const float4*)&S.hTc[2*og+17][pb4];
        float sa0[4], sa1[4], sb0[4], sb1[4];
        #pragma unroll
        for (int k = 0; k < 4; k++) {
            unpack2(accsA[k], sa0[k], sa1[k]);
            unpack2(accsB[k], sb0[k], sb1[k]);
        }
        float* houtb = h_out + b*CH_*L_;
        *(float4*)&houtb[(2*og   )*L_ + l0 + pb4] =
            make_float4(h0.x + sa0[0], h0.y + sa0[1], h0.z + sa0[2], h0.w + sa0[3]);
        *(float4*)&houtb[(2*og+ 1)*L_ + l0 + pb4] =
            make_float4(h1.x + sa1[0], h1.y + sa1[1], h1.z + sa1[2], h1.w + sa1[3]);
        *(float4*)&houtb[(2*og+16)*L_ + l0 + pb4] =
            make_float4(h2.x + sb0[0], h2.y + sb0[1], h2.z + sb0[2], h2.w + sb0[3]);
        *(float4*)&houtb[(2*og+17)*L_ + l0 + pb4] =
            make_float4(h3.x + sb1[0], h3.y + sb1[1], h3.z + sb1[2], h3.w + sb1[3]);
    }

    // ---- publish this tile's completion (release store after CTA barrier)
    __syncthreads();
    if (tid == 0)
        st_rel(&g_flags[i*NTILE + tile], 1);
}

// ---------------------------------------------------------------------------
// FC head: 128 -> 64 (relu) -> 10. PDL; resets g_flags/g_pool for next replay.
// ---------------------------------------------------------------------------
__global__ void fc_kernel(const float* __restrict__ fW1, const float* __restrict__ fb1,
                          const float* __restrict__ fW2, const float* __restrict__ fb2,
                          float* __restrict__ out)
{
    __shared__ float sw[64*129];
    __shared__ float ps[128], h1[64];
    const int b = blockIdx.x, tid = threadIdx.x;

    #pragma unroll 8
    for (int i = tid; i < 8192; i += 64) {
        int r = i >> 7, c = i & 127;
        sw[r*129 + c] = fW1[i];
    }
    float bias = fb1[tid];
    cudaGridDependencySynchronize();       // all chain CTAs (incl. pool) done

    ps[tid]      = g_pool[b*128 + tid];
    ps[tid + 64] = g_pool[b*128 + 64 + tid];
    __syncthreads();

    g_pool[b*128 + tid]      = 0.f;
    g_pool[b*128 + 64 + tid] = 0.f;
    for (int j = b*64 + tid; j < NBLK*NTILE; j += B_*64)
        g_flags[j] = 0;

    float acc = bias;
    #pragma unroll 16
    for (int k = 0; k < 128; k++) acc = fmaf(sw[tid*129 + k], ps[k], acc);
    h1[tid] = fmaxf(acc, 0.f);
    __syncthreads();
    if (tid < 10) {
        float a2 = fb2[tid];
        #pragma unroll 8
        for (int k = 0; k < 64; k++) a2 = fmaf(fW2[tid*64 + k], h1[k], a2);
        out[b*10 + tid] = a2;
    }
}

// ---------------------------------------------------------------------------
extern "C" void kernel_launch(void* const* d_in, const int* in_sizes, int n_in,
                              void* d_out, int out_size)
{
    const float* x   = (const float*)d_in[0];
    const float* W0  = (const float*)d_in[1];
    const float* b0  = (const float*)d_in[2];
    const float* Wd  = (const float*)d_in[3];   // (24, 64, 32, 2)
    const float* bd  = (const float*)d_in[4];   // (24, 64)
    const float* W1  = (const float*)d_in[5];   // (24, 32, 32)
    const float* b1  = (const float*)d_in[6];   // (24, 32)
    const float* Wf  = (const float*)d_in[7];
    const float* bf  = (const float*)d_in[8];
    const float* fW1 = (const float*)d_in[9];
    const float* fb1 = (const float*)d_in[10];
    const float* fW2 = (const float*)d_in[11];
    const float* fb2 = (const float*)d_in[12];
    float* out = (float*)d_out;

    static bool attr_done = false;
    if (!attr_done) {
        cudaFuncSetAttribute(chain_kernel,
            cudaFuncAttributeMaxDynamicSharedMemorySize, SMEM_BYTES);
        attr_done = true;
    }

    // 24 layers (layer 0 computes h_init from x) + fused pool, one grid
    chain_kernel<<<NGRID, NTHR, SMEM_BYTES>>>(x, W0, b0, Wd, bd, W1, b1, Wf, bf);

    // FC head with PDL: weight staging overlaps the chain tail
    cudaLaunchAttribute pdl[1];
    pdl[0].id = cudaLaunchAttributeProgrammaticStreamSerialization;
    pdl[0].val.programmaticStreamSerializationAllowed = 1;
    cudaLaunchConfig_t cfgF = {};
    cfgF.gridDim  = dim3(B_);
    cfgF.blockDim = dim3(64);
    cfgF.dynamicSmemBytes = 0;
    cfgF.stream = 0;
    cfgF.attrs = pdl;
    cfgF.numAttrs = 1;
    cudaLaunchKernelEx(&cfgF, fc_kernel, fW1, fb1, fW2, fb2, out);
}